// round 5
// baseline (speedup 1.0000x reference)
#include <cuda_runtime.h>
#include <cuda_bf16.h>

// Problem constants
#define SEQ     4096
#define BATCH   4
#define DMODEL  512
#define FFDIM   2048
#define MTOT    (BATCH*SEQ)        // 16384 rows total

// ---------------------------------------------------------------------------
// Scratch (static device globals: no allocation anywhere, per harness rules)
// ---------------------------------------------------------------------------
__device__ float g_q[(size_t)MTOT * DMODEL];            // Q, later reused for unify/ff2 out
__device__ float g_k[(size_t)MTOT * DMODEL];
__device__ float g_v[(size_t)MTOT * DMODEL];
__device__ float g_s[(size_t)BATCH * SEQ * SEQ];        // scores / probs (256 MB)
__device__ float g_attn[(size_t)MTOT * DMODEL];
__device__ float g_h[(size_t)MTOT * DMODEL];            // post-LN1 hidden
__device__ float g_ff[(size_t)MTOT * FFDIM];            // FF1 activation

// ---------------------------------------------------------------------------
// Generic 128x128x8 register-tiled SGEMM.
//   C[z] = alpha * (A[z] @ B[z] (or B[z]^T)) + bias (+ ReLU)
// A: row-major [M,K] (stride sA per batch z)
// B: row-major [K,N] if !TRANSB, row-major [N,K] if TRANSB (stride sB)
// C: row-major [M,N] (stride sC)
// Requires M%128==0, N%128==0, K%8==0 (true for all shapes here).
// 256 threads, 8x8 per-thread tile.
// ---------------------------------------------------------------------------
template<bool TRANSB, bool RELU>
__global__ __launch_bounds__(256) void gemm_k(
    const float* __restrict__ A, const float* __restrict__ Bm,
    const float* __restrict__ bias, float* __restrict__ C,
    int M, int N, int K,
    long long sA, long long sB, long long sC, float alpha)
{
    __shared__ float As[8][128];
    __shared__ float Bs[8][128];

    const float* Ab = A  + (long long)blockIdx.z * sA;
    const float* Bb = Bm + (long long)blockIdx.z * sB;
    float*       Cb = C  + (long long)blockIdx.z * sC;

    const int tid = threadIdx.x;
    const int tx  = tid & 15;     // 16 col-groups
    const int ty  = tid >> 4;     // 16 row-groups

    float acc[8][8];
#pragma unroll
    for (int i = 0; i < 8; i++)
#pragma unroll
        for (int j = 0; j < 8; j++) acc[i][j] = 0.f;

    // A tile load mapping: 128 rows x 8 k, float4 along K
    const int aRow = tid >> 1;
    const int aCol = (tid & 1) * 4;
    const float* Aload = Ab + ((long long)blockIdx.y * 128 + aRow) * K + aCol;

    // B tile load mapping
    const float* Bload;
    int bRow, bCol;
    if (TRANSB) {                       // B is [N,K]: load like A, transpose into Bs
        bRow = tid >> 1; bCol = (tid & 1) * 4;
        Bload = Bb + ((long long)blockIdx.x * 128 + bRow) * K + bCol;
    } else {                            // B is [K,N]: 8 rows x 128 cols, float4 along N
        bRow = tid >> 5; bCol = (tid & 31) * 4;
        Bload = Bb + (long long)bRow * N + blockIdx.x * 128 + bCol;
    }

    for (int k0 = 0; k0 < K; k0 += 8) {
        float4 a4 = *reinterpret_cast<const float4*>(Aload + k0);
        As[aCol + 0][aRow] = a4.x;
        As[aCol + 1][aRow] = a4.y;
        As[aCol + 2][aRow] = a4.z;
        As[aCol + 3][aRow] = a4.w;
        if (TRANSB) {
            float4 b4 = *reinterpret_cast<const float4*>(Bload + k0);
            Bs[bCol + 0][bRow] = b4.x;
            Bs[bCol + 1][bRow] = b4.y;
            Bs[bCol + 2][bRow] = b4.z;
            Bs[bCol + 3][bRow] = b4.w;
        } else {
            float4 b4 = *reinterpret_cast<const float4*>(Bload + (long long)k0 * N);
            *reinterpret_cast<float4*>(&Bs[bRow][bCol]) = b4;
        }
        __syncthreads();

#pragma unroll
        for (int kk = 0; kk < 8; kk++) {
            float4 a0 = *reinterpret_cast<const float4*>(&As[kk][ty * 8]);
            float4 a1 = *reinterpret_cast<const float4*>(&As[kk][ty * 8 + 4]);
            float4 b0 = *reinterpret_cast<const float4*>(&Bs[kk][tx * 8]);
            float4 b1 = *reinterpret_cast<const float4*>(&Bs[kk][tx * 8 + 4]);
            float ar[8] = {a0.x, a0.y, a0.z, a0.w, a1.x, a1.y, a1.z, a1.w};
            float br[8] = {b0.x, b0.y, b0.z, b0.w, b1.x, b1.y, b1.z, b1.w};
#pragma unroll
            for (int i = 0; i < 8; i++)
#pragma unroll
                for (int j = 0; j < 8; j++)
                    acc[i][j] = fmaf(ar[i], br[j], acc[i][j]);
        }
        __syncthreads();
    }

    // Epilogue: alpha scale, bias add, optional ReLU, vectorized store
#pragma unroll
    for (int i = 0; i < 8; i++) {
        long long row = (long long)blockIdx.y * 128 + ty * 8 + i;
#pragma unroll
        for (int j = 0; j < 8; j += 4) {
            int col = blockIdx.x * 128 + tx * 8 + j;
            float4 r;
            r.x = acc[i][j + 0] * alpha;
            r.y = acc[i][j + 1] * alpha;
            r.z = acc[i][j + 2] * alpha;
            r.w = acc[i][j + 3] * alpha;
            if (bias) {
                float4 bb = *reinterpret_cast<const float4*>(bias + col);
                r.x += bb.x; r.y += bb.y; r.z += bb.z; r.w += bb.w;
            }
            if (RELU) {
                r.x = fmaxf(r.x, 0.f); r.y = fmaxf(r.y, 0.f);
                r.z = fmaxf(r.z, 0.f); r.w = fmaxf(r.w, 0.f);
            }
            *reinterpret_cast<float4*>(Cb + row * (long long)N + col) = r;
        }
    }
}

// ---------------------------------------------------------------------------
// Row softmax over width 4096, one block per row, values held in registers.
// ---------------------------------------------------------------------------
__global__ __launch_bounds__(256) void softmax_k(float* __restrict__ S)
{
    long long row = blockIdx.x;
    float* p = S + row * (long long)SEQ;
    const int tid  = threadIdx.x;
    const int lane = tid & 31;
    const int warp = tid >> 5;
    __shared__ float red[8];

    float v[16];
    float mx = -1e30f;
#pragma unroll
    for (int i = 0; i < 16; i++) {
        v[i] = p[i * 256 + tid];
        mx = fmaxf(mx, v[i]);
    }
#pragma unroll
    for (int o = 16; o > 0; o >>= 1) mx = fmaxf(mx, __shfl_xor_sync(0xffffffffu, mx, o));
    if (!lane) red[warp] = mx;
    __syncthreads();
    mx = red[0];
#pragma unroll
    for (int w = 1; w < 8; w++) mx = fmaxf(mx, red[w]);
    __syncthreads();

    float sm = 0.f;
#pragma unroll
    for (int i = 0; i < 16; i++) {
        v[i] = __expf(v[i] - mx);
        sm += v[i];
    }
#pragma unroll
    for (int o = 16; o > 0; o >>= 1) sm += __shfl_xor_sync(0xffffffffu, sm, o);
    if (!lane) red[warp] = sm;
    __syncthreads();
    float total = red[0] + red[1] + red[2] + red[3] + red[4] + red[5] + red[6] + red[7];
    float inv = __frcp_rn(total);
#pragma unroll
    for (int i = 0; i < 16; i++) p[i * 256 + tid] = v[i] * inv;
}

// ---------------------------------------------------------------------------
// out = LayerNorm(X + U) * g + b     (one 128-thread block per 512-wide row)
// ---------------------------------------------------------------------------
__global__ __launch_bounds__(128) void add_ln_k(
    const float* __restrict__ X, const float* __restrict__ U,
    const float* __restrict__ g, const float* __restrict__ b,
    float* __restrict__ out)
{
    long long row = blockIdx.x;
    const int tid  = threadIdx.x;
    const int lane = tid & 31;
    const int warp = tid >> 5;
    __shared__ float red[4];

    float4 xv = reinterpret_cast<const float4*>(X + row * DMODEL)[tid];
    float4 uv = reinterpret_cast<const float4*>(U + row * DMODEL)[tid];
    float4 s = make_float4(xv.x + uv.x, xv.y + uv.y, xv.z + uv.z, xv.w + uv.w);

    float p = s.x + s.y + s.z + s.w;
#pragma unroll
    for (int o = 16; o > 0; o >>= 1) p += __shfl_xor_sync(0xffffffffu, p, o);
    if (!lane) red[warp] = p;
    __syncthreads();
    float mu = (red[0] + red[1] + red[2] + red[3]) * (1.f / DMODEL);
    __syncthreads();

    float dx = s.x - mu, dy = s.y - mu, dz = s.z - mu, dw = s.w - mu;
    p = dx * dx + dy * dy + dz * dz + dw * dw;
#pragma unroll
    for (int o = 16; o > 0; o >>= 1) p += __shfl_xor_sync(0xffffffffu, p, o);
    if (!lane) red[warp] = p;
    __syncthreads();
    float var = (red[0] + red[1] + red[2] + red[3]) * (1.f / DMODEL);
    float inv = rsqrtf(var + 1e-5f);

    float4 gv = reinterpret_cast<const float4*>(g)[tid];
    float4 bv = reinterpret_cast<const float4*>(b)[tid];
    float4 o4;
    o4.x = dx * inv * gv.x + bv.x;
    o4.y = dy * inv * gv.y + bv.y;
    o4.z = dz * inv * gv.z + bv.z;
    o4.w = dw * inv * gv.w + bv.w;
    reinterpret_cast<float4*>(out + row * DMODEL)[tid] = o4;
}

// ---------------------------------------------------------------------------
// Launcher
// ---------------------------------------------------------------------------
extern "C" void kernel_launch(void* const* d_in, const int* in_sizes, int n_in,
                              void* d_out, int out_size)
{
    (void)in_sizes; (void)n_in; (void)out_size;
    const float* x     = (const float*)d_in[0];
    const float* Wq_w  = (const float*)d_in[1];
    const float* Wq_b  = (const float*)d_in[2];
    const float* Wk_w  = (const float*)d_in[3];
    const float* Wk_b  = (const float*)d_in[4];
    const float* Wv_w  = (const float*)d_in[5];
    const float* Wv_b  = (const float*)d_in[6];
    const float* Wu_w  = (const float*)d_in[7];
    const float* Wu_b  = (const float*)d_in[8];
    const float* ln1_g = (const float*)d_in[9];
    const float* ln1_b = (const float*)d_in[10];
    const float* ff1_w = (const float*)d_in[11];
    const float* ff1_b = (const float*)d_in[12];
    const float* ff2_w = (const float*)d_in[13];
    const float* ff2_b = (const float*)d_in[14];
    const float* ln2_g = (const float*)d_in[15];
    const float* ln2_b = (const float*)d_in[16];
    float* out = (float*)d_out;

    void *pq, *pk, *pv, *ps, *pa, *ph, *pf;
    cudaGetSymbolAddress(&pq, g_q);
    cudaGetSymbolAddress(&pk, g_k);
    cudaGetSymbolAddress(&pv, g_v);
    cudaGetSymbolAddress(&ps, g_s);
    cudaGetSymbolAddress(&pa, g_attn);
    cudaGetSymbolAddress(&ph, g_h);
    cudaGetSymbolAddress(&pf, g_ff);
    float* q = (float*)pq; float* k = (float*)pk; float* v = (float*)pv;
    float* s = (float*)ps; float* attn = (float*)pa;
    float* h = (float*)ph; float* f = (float*)pf;

    const dim3 T(256);
    const long long QKV_S = (long long)SEQ * DMODEL;   // per-batch stride in q/k/v/attn
    const long long S_S   = (long long)SEQ * SEQ;      // per-batch stride in scores

    // Q, K, V projections: [16384,512] @ [512,512] + bias
    gemm_k<false, false><<<dim3(DMODEL/128, MTOT/128, 1), T>>>(
        x, Wq_w, Wq_b, q, MTOT, DMODEL, DMODEL, 0, 0, 0, 1.f);
    gemm_k<false, false><<<dim3(DMODEL/128, MTOT/128, 1), T>>>(
        x, Wk_w, Wk_b, k, MTOT, DMODEL, DMODEL, 0, 0, 0, 1.f);
    gemm_k<false, false><<<dim3(DMODEL/128, MTOT/128, 1), T>>>(
        x, Wv_w, Wv_b, v, MTOT, DMODEL, DMODEL, 0, 0, 0, 1.f);

    // scores[b] = Q_b @ K_b^T / sqrt(64)
    gemm_k<true, false><<<dim3(SEQ/128, SEQ/128, BATCH), T>>>(
        q, k, nullptr, s, SEQ, SEQ, DMODEL, QKV_S, QKV_S, S_S, 0.125f);

    // row softmax (in place)
    softmax_k<<<MTOT, 256>>>(s);

    // attn[b] = P_b @ V_b   (M=4096, N=512, K=4096)
    gemm_k<false, false><<<dim3(DMODEL/128, SEQ/128, BATCH), T>>>(
        s, v, nullptr, attn, SEQ, DMODEL, SEQ, S_S, QKV_S, QKV_S, 1.f);

    // unify: attn @ Wu + b  -> reuse q buffer
    gemm_k<false, false><<<dim3(DMODEL/128, MTOT/128, 1), T>>>(
        attn, Wu_w, Wu_b, q, MTOT, DMODEL, DMODEL, 0, 0, 0, 1.f);

    // h = LN1(x + unified)
    add_ln_k<<<MTOT, 128>>>(x, q, ln1_g, ln1_b, h);

    // ffwd = relu(h @ ff1 + b1) @ ff2 + b2
    gemm_k<false, true><<<dim3(FFDIM/128, MTOT/128, 1), T>>>(
        h, ff1_w, ff1_b, f, MTOT, FFDIM, DMODEL, 0, 0, 0, 1.f);
    gemm_k<false, false><<<dim3(DMODEL/128, MTOT/128, 1), T>>>(
        f, ff2_w, ff2_b, q, MTOT, DMODEL, FFDIM, 0, 0, 0, 1.f);

    // out = LN2(h + ffwd)
    add_ln_k<<<MTOT, 128>>>(h, q, ln2_g, ln2_b, out);
}

// round 7
// speedup vs baseline: 1.0019x; 1.0019x over previous
#include <cuda_runtime.h>
#include <cuda_bf16.h>

// Problem constants
#define SEQ     4096
#define BATCH   4
#define DMODEL  512
#define FFDIM   2048
#define MTOT    (BATCH*SEQ)        // 16384 rows total

// ---------------------------------------------------------------------------
// Scratch (static device globals: no allocation anywhere, per harness rules)
// ---------------------------------------------------------------------------
__device__ float g_q[(size_t)MTOT * DMODEL];            // Q, later reused for unify/ff2 out
__device__ float g_k[(size_t)MTOT * DMODEL];
__device__ float g_v[(size_t)MTOT * DMODEL];
__device__ float g_s[(size_t)BATCH * SEQ * SEQ];        // scores / probs (256 MB)
__device__ float g_attn[(size_t)MTOT * DMODEL];
__device__ float g_h[(size_t)MTOT * DMODEL];            // post-LN1 hidden
__device__ float g_ff[(size_t)MTOT * FFDIM];            // FF1 activation

// ---------------------------------------------------------------------------
// Generic 128x128x8 register-tiled SGEMM.
//   C[z] = alpha * (A[z] @ B[z] (or B[z]^T)) + bias (+ ReLU)
// A: row-major [M,K] (stride sA per batch z)
// B: row-major [K,N] if !TRANSB, row-major [N,K] if TRANSB (stride sB)
// C: row-major [M,N] (stride sC)
// Requires M%128==0, N%128==0, K%8==0 (true for all shapes here).
// 256 threads, 8x8 per-thread tile.
// ---------------------------------------------------------------------------
template<bool TRANSB, bool RELU>
__global__ __launch_bounds__(256) void gemm_k(
    const float* __restrict__ A, const float* __restrict__ Bm,
    const float* __restrict__ bias, float* __restrict__ C,
    int M, int N, int K,
    long long sA, long long sB, long long sC, float alpha)
{
    __shared__ float As[8][128];
    __shared__ float Bs[8][128];

    const float* Ab = A  + (long long)blockIdx.z * sA;
    const float* Bb = Bm + (long long)blockIdx.z * sB;
    float*       Cb = C  + (long long)blockIdx.z * sC;

    const int tid = threadIdx.x;
    const int tx  = tid & 15;     // 16 col-groups
    const int ty  = tid >> 4;     // 16 row-groups

    float acc[8][8];
#pragma unroll
    for (int i = 0; i < 8; i++)
#pragma unroll
        for (int j = 0; j < 8; j++) acc[i][j] = 0.f;

    // A tile load mapping: 128 rows x 8 k, float4 along K
    const int aRow = tid >> 1;
    const int aCol = (tid & 1) * 4;
    const float* Aload = Ab + ((long long)blockIdx.y * 128 + aRow) * K + aCol;

    // B tile load mapping
    const float* Bload;
    int bRow, bCol;
    if (TRANSB) {                       // B is [N,K]: load like A, transpose into Bs
        bRow = tid >> 1; bCol = (tid & 1) * 4;
        Bload = Bb + ((long long)blockIdx.x * 128 + bRow) * K + bCol;
    } else {                            // B is [K,N]: 8 rows x 128 cols, float4 along N
        bRow = tid >> 5; bCol = (tid & 31) * 4;
        Bload = Bb + (long long)bRow * N + blockIdx.x * 128 + bCol;
    }

    for (int k0 = 0; k0 < K; k0 += 8) {
        float4 a4 = *reinterpret_cast<const float4*>(Aload + k0);
        As[aCol + 0][aRow] = a4.x;
        As[aCol + 1][aRow] = a4.y;
        As[aCol + 2][aRow] = a4.z;
        As[aCol + 3][aRow] = a4.w;
        if (TRANSB) {
            float4 b4 = *reinterpret_cast<const float4*>(Bload + k0);
            Bs[bCol + 0][bRow] = b4.x;
            Bs[bCol + 1][bRow] = b4.y;
            Bs[bCol + 2][bRow] = b4.z;
            Bs[bCol + 3][bRow] = b4.w;
        } else {
            float4 b4 = *reinterpret_cast<const float4*>(Bload + (long long)k0 * N);
            *reinterpret_cast<float4*>(&Bs[bRow][bCol]) = b4;
        }
        __syncthreads();

#pragma unroll
        for (int kk = 0; kk < 8; kk++) {
            float4 a0 = *reinterpret_cast<const float4*>(&As[kk][ty * 8]);
            float4 a1 = *reinterpret_cast<const float4*>(&As[kk][ty * 8 + 4]);
            float4 b0 = *reinterpret_cast<const float4*>(&Bs[kk][tx * 8]);
            float4 b1 = *reinterpret_cast<const float4*>(&Bs[kk][tx * 8 + 4]);
            float ar[8] = {a0.x, a0.y, a0.z, a0.w, a1.x, a1.y, a1.z, a1.w};
            float br[8] = {b0.x, b0.y, b0.z, b0.w, b1.x, b1.y, b1.z, b1.w};
#pragma unroll
            for (int i = 0; i < 8; i++)
#pragma unroll
                for (int j = 0; j < 8; j++)
                    acc[i][j] = fmaf(ar[i], br[j], acc[i][j]);
        }
        __syncthreads();
    }

    // Epilogue: alpha scale, bias add, optional ReLU, vectorized store
#pragma unroll
    for (int i = 0; i < 8; i++) {
        long long row = (long long)blockIdx.y * 128 + ty * 8 + i;
#pragma unroll
        for (int j = 0; j < 8; j += 4) {
            int col = blockIdx.x * 128 + tx * 8 + j;
            float4 r;
            r.x = acc[i][j + 0] * alpha;
            r.y = acc[i][j + 1] * alpha;
            r.z = acc[i][j + 2] * alpha;
            r.w = acc[i][j + 3] * alpha;
            if (bias) {
                float4 bb = *reinterpret_cast<const float4*>(bias + col);
                r.x += bb.x; r.y += bb.y; r.z += bb.z; r.w += bb.w;
            }
            if (RELU) {
                r.x = fmaxf(r.x, 0.f); r.y = fmaxf(r.y, 0.f);
                r.z = fmaxf(r.z, 0.f); r.w = fmaxf(r.w, 0.f);
            }
            *reinterpret_cast<float4*>(Cb + row * (long long)N + col) = r;
        }
    }
}

// ---------------------------------------------------------------------------
// Row softmax over width 4096, one block per row, values held in registers.
// ---------------------------------------------------------------------------
__global__ __launch_bounds__(256) void softmax_k(float* __restrict__ S)
{
    long long row = blockIdx.x;
    float* p = S + row * (long long)SEQ;
    const int tid  = threadIdx.x;
    const int lane = tid & 31;
    const int warp = tid >> 5;
    __shared__ float red[8];

    float v[16];
    float mx = -1e30f;
#pragma unroll
    for (int i = 0; i < 16; i++) {
        v[i] = p[i * 256 + tid];
        mx = fmaxf(mx, v[i]);
    }
#pragma unroll
    for (int o = 16; o > 0; o >>= 1) mx = fmaxf(mx, __shfl_xor_sync(0xffffffffu, mx, o));
    if (!lane) red[warp] = mx;
    __syncthreads();
    mx = red[0];
#pragma unroll
    for (int w = 1; w < 8; w++) mx = fmaxf(mx, red[w]);
    __syncthreads();

    float sm = 0.f;
#pragma unroll
    for (int i = 0; i < 16; i++) {
        v[i] = __expf(v[i] - mx);
        sm += v[i];
    }
#pragma unroll
    for (int o = 16; o > 0; o >>= 1) sm += __shfl_xor_sync(0xffffffffu, sm, o);
    if (!lane) red[warp] = sm;
    __syncthreads();
    float total = red[0] + red[1] + red[2] + red[3] + red[4] + red[5] + red[6] + red[7];
    float inv = __frcp_rn(total);
#pragma unroll
    for (int i = 0; i < 16; i++) p[i * 256 + tid] = v[i] * inv;
}

// ---------------------------------------------------------------------------
// out = LayerNorm(X + U) * g + b     (one 128-thread block per 512-wide row)
// ---------------------------------------------------------------------------
__global__ __launch_bounds__(128) void add_ln_k(
    const float* __restrict__ X, const float* __restrict__ U,
    const float* __restrict__ g, const float* __restrict__ b,
    float* __restrict__ out)
{
    long long row = blockIdx.x;
    const int tid  = threadIdx.x;
    const int lane = tid & 31;
    const int warp = tid >> 5;
    __shared__ float red[4];

    float4 xv = reinterpret_cast<const float4*>(X + row * DMODEL)[tid];
    float4 uv = reinterpret_cast<const float4*>(U + row * DMODEL)[tid];
    float4 s = make_float4(xv.x + uv.x, xv.y + uv.y, xv.z + uv.z, xv.w + uv.w);

    float p = s.x + s.y + s.z + s.w;
#pragma unroll
    for (int o = 16; o > 0; o >>= 1) p += __shfl_xor_sync(0xffffffffu, p, o);
    if (!lane) red[warp] = p;
    __syncthreads();
    float mu = (red[0] + red[1] + red[2] + red[3]) * (1.f / DMODEL);
    __syncthreads();

    float dx = s.x - mu, dy = s.y - mu, dz = s.z - mu, dw = s.w - mu;
    p = dx * dx + dy * dy + dz * dz + dw * dw;
#pragma unroll
    for (int o = 16; o > 0; o >>= 1) p += __shfl_xor_sync(0xffffffffu, p, o);
    if (!lane) red[warp] = p;
    __syncthreads();
    float var = (red[0] + red[1] + red[2] + red[3]) * (1.f / DMODEL);
    float inv = rsqrtf(var + 1e-5f);

    float4 gv = reinterpret_cast<const float4*>(g)[tid];
    float4 bv = reinterpret_cast<const float4*>(b)[tid];
    float4 o4;
    o4.x = dx * inv * gv.x + bv.x;
    o4.y = dy * inv * gv.y + bv.y;
    o4.z = dz * inv * gv.z + bv.z;
    o4.w = dw * inv * gv.w + bv.w;
    reinterpret_cast<float4*>(out + row * DMODEL)[tid] = o4;
}

// ---------------------------------------------------------------------------
// Launcher
// ---------------------------------------------------------------------------
extern "C" void kernel_launch(void* const* d_in, const int* in_sizes, int n_in,
                              void* d_out, int out_size)
{
    (void)in_sizes; (void)n_in; (void)out_size;
    const float* x     = (const float*)d_in[0];
    const float* Wq_w  = (const float*)d_in[1];
    const float* Wq_b  = (const float*)d_in[2];
    const float* Wk_w  = (const float*)d_in[3];
    const float* Wk_b  = (const float*)d_in[4];
    const float* Wv_w  = (const float*)d_in[5];
    const float* Wv_b  = (const float*)d_in[6];
    const float* Wu_w  = (const float*)d_in[7];
    const float* Wu_b  = (const float*)d_in[8];
    const float* ln1_g = (const float*)d_in[9];
    const float* ln1_b = (const float*)d_in[10];
    const float* ff1_w = (const float*)d_in[11];
    const float* ff1_b = (const float*)d_in[12];
    const float* ff2_w = (const float*)d_in[13];
    const float* ff2_b = (const float*)d_in[14];
    const float* ln2_g = (const float*)d_in[15];
    const float* ln2_b = (const float*)d_in[16];
    float* out = (float*)d_out;

    void *pq, *pk, *pv, *ps, *pa, *ph, *pf;
    cudaGetSymbolAddress(&pq, g_q);
    cudaGetSymbolAddress(&pk, g_k);
    cudaGetSymbolAddress(&pv, g_v);
    cudaGetSymbolAddress(&ps, g_s);
    cudaGetSymbolAddress(&pa, g_attn);
    cudaGetSymbolAddress(&ph, g_h);
    cudaGetSymbolAddress(&pf, g_ff);
    float* q = (float*)pq; float* k = (float*)pk; float* v = (float*)pv;
    float* s = (float*)ps; float* attn = (float*)pa;
    float* h = (float*)ph; float* f = (float*)pf;

    const dim3 T(256);
    const long long QKV_S = (long long)SEQ * DMODEL;   // per-batch stride in q/k/v/attn
    const long long S_S   = (long long)SEQ * SEQ;      // per-batch stride in scores

    // Q, K, V projections: [16384,512] @ [512,512] + bias
    gemm_k<false, false><<<dim3(DMODEL/128, MTOT/128, 1), T>>>(
        x, Wq_w, Wq_b, q, MTOT, DMODEL, DMODEL, 0, 0, 0, 1.f);
    gemm_k<false, false><<<dim3(DMODEL/128, MTOT/128, 1), T>>>(
        x, Wk_w, Wk_b, k, MTOT, DMODEL, DMODEL, 0, 0, 0, 1.f);
    gemm_k<false, false><<<dim3(DMODEL/128, MTOT/128, 1), T>>>(
        x, Wv_w, Wv_b, v, MTOT, DMODEL, DMODEL, 0, 0, 0, 1.f);

    // scores[b] = Q_b @ K_b^T / sqrt(64)
    gemm_k<true, false><<<dim3(SEQ/128, SEQ/128, BATCH), T>>>(
        q, k, nullptr, s, SEQ, SEQ, DMODEL, QKV_S, QKV_S, S_S, 0.125f);

    // row softmax (in place)
    softmax_k<<<MTOT, 256>>>(s);

    // attn[b] = P_b @ V_b   (M=4096, N=512, K=4096)
    gemm_k<false, false><<<dim3(DMODEL/128, SEQ/128, BATCH), T>>>(
        s, v, nullptr, attn, SEQ, DMODEL, SEQ, S_S, QKV_S, QKV_S, 1.f);

    // unify: attn @ Wu + b  -> reuse q buffer
    gemm_k<false, false><<<dim3(DMODEL/128, MTOT/128, 1), T>>>(
        attn, Wu_w, Wu_b, q, MTOT, DMODEL, DMODEL, 0, 0, 0, 1.f);

    // h = LN1(x + unified)
    add_ln_k<<<MTOT, 128>>>(x, q, ln1_g, ln1_b, h);

    // ffwd = relu(h @ ff1 + b1) @ ff2 + b2
    gemm_k<false, true><<<dim3(FFDIM/128, MTOT/128, 1), T>>>(
        h, ff1_w, ff1_b, f, MTOT, FFDIM, DMODEL, 0, 0, 0, 1.f);
    gemm_k<false, false><<<dim3(DMODEL/128, MTOT/128, 1), T>>>(
        f, ff2_w, ff2_b, q, MTOT, DMODEL, FFDIM, 0, 0, 0, 1.f);

    // out = LN2(h + ffwd)
    add_ln_k<<<MTOT, 128>>>(h, q, ln2_g, ln2_b, out);
}

// round 9
// speedup vs baseline: 2.6846x; 2.6795x over previous
#include <cuda_runtime.h>
#include <cuda_bf16.h>
#include <cstdint>

#define SEQ     4096
#define BATCH   4
#define DMODEL  512
#define FFDIM   2048
#define MTOT    (BATCH*SEQ)

// GEMM tile config (HMMA mma.sync path; target sm_103 has no tcgen05)
#define BMT 128
#define BNT 128
#define BKT 32
#define NST 3
#define ASZ 8192              // 128 rows * 64B (32 bf16)
#define STG (2*ASZ)           // A + B per stage

// ---------------- scratch ----------------
__device__ __align__(256) float         g_s  [(size_t)BATCH*SEQ*SEQ];
__device__ __align__(256) __nv_bfloat16 g_xh [(size_t)MTOT*DMODEL], g_xl [(size_t)MTOT*DMODEL];
__device__ __align__(256) __nv_bfloat16 g_qh [(size_t)MTOT*DMODEL], g_ql [(size_t)MTOT*DMODEL];
__device__ __align__(256) __nv_bfloat16 g_kh [(size_t)MTOT*DMODEL], g_kl [(size_t)MTOT*DMODEL];
__device__ __align__(256) float         g_vf [(size_t)MTOT*DMODEL];
__device__ __align__(256) __nv_bfloat16 g_vth[(size_t)MTOT*DMODEL], g_vtl[(size_t)MTOT*DMODEL];
__device__ __align__(256) __nv_bfloat16 g_ah [(size_t)MTOT*DMODEL], g_al [(size_t)MTOT*DMODEL];
__device__ __align__(256) float         g_u  [(size_t)MTOT*DMODEL];
__device__ __align__(256) float         g_h  [(size_t)MTOT*DMODEL];
__device__ __align__(256) __nv_bfloat16 g_hh [(size_t)MTOT*DMODEL], g_hl [(size_t)MTOT*DMODEL];
__device__ __align__(256) __nv_bfloat16 g_fh [(size_t)MTOT*FFDIM],  g_fl [(size_t)MTOT*FFDIM];
__device__ __align__(256) __nv_bfloat16 g_wqh[DMODEL*DMODEL], g_wql[DMODEL*DMODEL];
__device__ __align__(256) __nv_bfloat16 g_wkh[DMODEL*DMODEL], g_wkl[DMODEL*DMODEL];
__device__ __align__(256) __nv_bfloat16 g_wvh[DMODEL*DMODEL], g_wvl[DMODEL*DMODEL];
__device__ __align__(256) __nv_bfloat16 g_wuh[DMODEL*DMODEL], g_wul[DMODEL*DMODEL];
__device__ __align__(256) __nv_bfloat16 g_f1h[FFDIM*DMODEL],  g_f1l[FFDIM*DMODEL];
__device__ __align__(256) __nv_bfloat16 g_f2h[DMODEL*FFDIM],  g_f2l[DMODEL*FFDIM];

// ---------------- PTX helpers (all sm_80+ base-target legal) ----------------
static __device__ __forceinline__ uint32_t smem_u32(const void* p) {
    uint32_t a;
    asm("{ .reg .u64 t; cvta.to.shared.u64 t, %1; cvt.u32.u64 %0, t; }" : "=r"(a) : "l"(p));
    return a;
}
#define CP_ASYNC16(saddr, gptr) \
    asm volatile("cp.async.cg.shared.global [%0], [%1], 16;" :: "r"(saddr), "l"(gptr) : "memory")
#define CP_COMMIT() asm volatile("cp.async.commit_group;" ::: "memory")
#define CP_WAIT1()  asm volatile("cp.async.wait_group 1;"  ::: "memory")

#define LDSM4(r, addr) \
    asm volatile("ldmatrix.sync.aligned.m8n8.x4.shared.b16 {%0,%1,%2,%3}, [%4];" \
        : "=r"((r)[0]), "=r"((r)[1]), "=r"((r)[2]), "=r"((r)[3]) : "r"(addr))

#define MMA16816(c, a, b) \
    asm volatile("mma.sync.aligned.m16n8k16.row.col.f32.bf16.bf16.f32 " \
        "{%0,%1,%2,%3}, {%4,%5,%6,%7}, {%8,%9}, {%0,%1,%2,%3};" \
        : "+f"((c)[0]), "+f"((c)[1]), "+f"((c)[2]), "+f"((c)[3]) \
        : "r"((a)[0]), "r"((a)[1]), "r"((a)[2]), "r"((a)[3]), "r"((b)[0]), "r"((b)[1]))

static __device__ __forceinline__ void split_hl(float v, __nv_bfloat16& h, __nv_bfloat16& l) {
    h = __float2bfloat16(v);
    l = __float2bfloat16(v - __bfloat162float(h));
}
static __device__ __forceinline__ uint32_t pack2(__nv_bfloat16 a, __nv_bfloat16 b) {
    return (uint32_t)__bfloat16_as_ushort(a) | ((uint32_t)__bfloat16_as_ushort(b) << 16);
}

// ---------------------------------------------------------------------------
// HMMA GEMM, hi/lo 3-phase. A:[M,K] K-major (lda), B:[N,K] K-major (ldb).
// D = alpha*(sum of 3 phases) + bias; outputs fp32 and/or bf16 hi/lo (ld=N_).
// CTA 128x128, BK=32, 3-stage cp.async, 8 warps (2M x 4N), warp tile 64x32.
// ---------------------------------------------------------------------------
template<bool RELU>
__global__ void __launch_bounds__(256, 2) mma_gemm(
    const __nv_bfloat16* __restrict__ Ahi, const __nv_bfloat16* __restrict__ Alo,
    long long lda, long long sAz,
    const __nv_bfloat16* __restrict__ Bhi, const __nv_bfloat16* __restrict__ Blo,
    long long ldb, long long sBz,
    const float* __restrict__ bias, float alpha,
    float* __restrict__ outF, __nv_bfloat16* __restrict__ outHi, __nv_bfloat16* __restrict__ outLo,
    int N_, long long sCz, int K)
{
    __shared__ __align__(1024) char smem[NST*STG];   // 49152 B
    const uint32_t sbase = smem_u32(smem);
    const int tid  = threadIdx.x;
    const int lane = tid & 31;
    const int wid  = tid >> 5;
    const int warp_m = (wid & 1) * 64;
    const int warp_n = (wid >> 1) * 32;

    const long long z    = blockIdx.z;
    const long long arow = (long long)blockIdx.y * BMT;
    const long long brow = (long long)blockIdx.x * BNT;

    const __nv_bfloat16* Ahi_z = Ahi + z * sAz;
    const __nv_bfloat16* Alo_z = Alo + z * sAz;
    const __nv_bfloat16* Bhi_z = Bhi + z * sBz;
    const __nv_bfloat16* Blo_z = Blo + z * sBz;

    float acc[4][4][4];
#pragma unroll
    for (int i = 0; i < 4; i++)
#pragma unroll
        for (int j = 0; j < 4; j++)
#pragma unroll
            for (int q = 0; q < 4; q++) acc[i][j][q] = 0.f;

    // per-thread cp.async slots: A tile 512 16B-chunks / 256 thr = 2, same for B
    const int r0 = tid >> 2,         c0 = tid & 3;
    const int r1 = (tid + 256) >> 2, c1 = (tid + 256) & 3;
    const uint32_t sw0 = r0*64 + (((c0 ^ ((r0 >> 1) & 3)) << 4));
    const uint32_t sw1 = r1*64 + (((c1 ^ ((r1 >> 1) & 3)) << 4));
    const long long gA0 = (arow + r0) * lda + c0*8;
    const long long gA1 = (arow + r1) * lda + c1*8;
    const long long gB0 = (brow + r0) * ldb + c0*8;
    const long long gB1 = (brow + r1) * ldb + c1*8;

    const int kcPer = K >> 5;        // 32-wide K chunks per phase
    const int nch   = 3 * kcPer;

#define ISSUE(ch) { \
        const int st_ = (ch) % NST; \
        const int ph_ = (ch) / kcPer; \
        const long long kof_ = (long long)((ch) - ph_*kcPer) * 32; \
        const __nv_bfloat16* Ap_ = (ph_ == 2) ? Alo_z : Ahi_z; \
        const __nv_bfloat16* Bp_ = (ph_ == 1) ? Blo_z : Bhi_z; \
        const uint32_t sA_ = sbase + st_*STG; \
        const uint32_t sB_ = sA_ + ASZ; \
        CP_ASYNC16(sA_ + sw0, Ap_ + gA0 + kof_); \
        CP_ASYNC16(sA_ + sw1, Ap_ + gA1 + kof_); \
        CP_ASYNC16(sB_ + sw0, Bp_ + gB0 + kof_); \
        CP_ASYNC16(sB_ + sw1, Bp_ + gB1 + kof_); }

    ISSUE(0); CP_COMMIT();
    ISSUE(1); CP_COMMIT();

    // ldmatrix per-thread bases
    const int rA   = lane & 15;
    const int kcA  = lane >> 4;            // 0/1 -> k chunk within k16
    const int swzA = (rA >> 1) & 3;
    const uint32_t aBase = (uint32_t)(warp_m + rA) * 64;
    const int rB   = ((lane >> 4) << 3) + (lane & 7);
    const int kcB  = (lane >> 3) & 1;
    const int swzB = (rB >> 1) & 3;
    const uint32_t bBase = (uint32_t)(warp_n + rB) * 64;

#pragma unroll 1
    for (int j = 0; j < nch; j++) {
        CP_WAIT1();
        __syncthreads();
        if (j + 2 < nch) { ISSUE(j + 2); }
        CP_COMMIT();

        const uint32_t sA = sbase + (j % NST) * STG;
        const uint32_t sB = sA + ASZ;
#pragma unroll
        for (int ks = 0; ks < 2; ks++) {
            uint32_t af[4][4];
            uint32_t bf[4][2];
#pragma unroll
            for (int mt = 0; mt < 4; mt++) {
                uint32_t addr = sA + aBase + mt*1024 + ((uint32_t)((ks*2 + kcA) ^ swzA) << 4);
                LDSM4(af[mt], addr);
            }
#pragma unroll
            for (int nt2 = 0; nt2 < 2; nt2++) {
                uint32_t r[4];
                uint32_t addr = sB + bBase + nt2*1024 + ((uint32_t)((ks*2 + kcB) ^ swzB) << 4);
                LDSM4(r, addr);
                bf[2*nt2][0]   = r[0]; bf[2*nt2][1]   = r[1];
                bf[2*nt2+1][0] = r[2]; bf[2*nt2+1][1] = r[3];
            }
#pragma unroll
            for (int mt = 0; mt < 4; mt++)
#pragma unroll
                for (int nt = 0; nt < 4; nt++)
                    MMA16816(acc[mt][nt], af[mt], bf[nt]);
        }
    }
#undef ISSUE

    // -------- epilogue --------
    const long long mBase = arow + warp_m + (lane >> 2);
    const int       nBase = (int)brow + warp_n + (lane & 3) * 2;
    const long long czB   = z * sCz;
#pragma unroll
    for (int mt = 0; mt < 4; mt++) {
        const long long ra = mBase + mt*16;
        const long long rb = ra + 8;
#pragma unroll
        for (int nt = 0; nt < 4; nt++) {
            const int col = nBase + nt*8;
            float v0 = acc[mt][nt][0] * alpha;
            float v1 = acc[mt][nt][1] * alpha;
            float v2 = acc[mt][nt][2] * alpha;
            float v3 = acc[mt][nt][3] * alpha;
            if (bias) {
                float2 bb = *reinterpret_cast<const float2*>(bias + col);
                v0 += bb.x; v1 += bb.y; v2 += bb.x; v3 += bb.y;
            }
            if (RELU) {
                v0 = fmaxf(v0, 0.f); v1 = fmaxf(v1, 0.f);
                v2 = fmaxf(v2, 0.f); v3 = fmaxf(v3, 0.f);
            }
            if (outF) {
                *reinterpret_cast<float2*>(outF + czB + ra*N_ + col) = make_float2(v0, v1);
                *reinterpret_cast<float2*>(outF + czB + rb*N_ + col) = make_float2(v2, v3);
            }
            if (outHi) {
                __nv_bfloat16 h0,l0,h1,l1,h2,l2,h3,l3;
                split_hl(v0,h0,l0); split_hl(v1,h1,l1);
                split_hl(v2,h2,l2); split_hl(v3,h3,l3);
                *reinterpret_cast<uint32_t*>(outHi + czB + ra*N_ + col) = pack2(h0, h1);
                *reinterpret_cast<uint32_t*>(outLo + czB + ra*N_ + col) = pack2(l0, l1);
                *reinterpret_cast<uint32_t*>(outHi + czB + rb*N_ + col) = pack2(h2, h3);
                *reinterpret_cast<uint32_t*>(outLo + czB + rb*N_ + col) = pack2(l2, l3);
            }
        }
    }
}

// fp32 -> bf16 hi/lo elementwise
__global__ void __launch_bounds__(256) conv_hl(
    const float* __restrict__ in, __nv_bfloat16* __restrict__ oh,
    __nv_bfloat16* __restrict__ ol, int n4)
{
    int i = blockIdx.x * 256 + threadIdx.x;
    if (i >= n4) return;
    float4 v = reinterpret_cast<const float4*>(in)[i];
    __nv_bfloat16 h0,l0,h1,l1,h2,l2,h3,l3;
    split_hl(v.x,h0,l0); split_hl(v.y,h1,l1); split_hl(v.z,h2,l2); split_hl(v.w,h3,l3);
    reinterpret_cast<uint2*>(oh)[i] = make_uint2(pack2(h0,h1), pack2(h2,h3));
    reinterpret_cast<uint2*>(ol)[i] = make_uint2(pack2(l0,l1), pack2(l2,l3));
}

// transpose + hi/lo: in fp32 [R,C] -> out bf16 [C,R]
__global__ void tconv(
    const float* __restrict__ in, long long sIn,
    __nv_bfloat16* __restrict__ oh, __nv_bfloat16* __restrict__ ol, long long sOut,
    int R, int C)
{
    __shared__ float t[32][33];
    const int c0 = blockIdx.x * 32, r0 = blockIdx.y * 32;
    in += blockIdx.z * sIn; oh += blockIdx.z * sOut; ol += blockIdx.z * sOut;
#pragma unroll
    for (int dy = 0; dy < 32; dy += 8)
        t[threadIdx.y + dy][threadIdx.x] =
            in[(long long)(r0 + threadIdx.y + dy) * C + c0 + threadIdx.x];
    __syncthreads();
#pragma unroll
    for (int dy = 0; dy < 32; dy += 8) {
        float v = t[threadIdx.x][threadIdx.y + dy];
        __nv_bfloat16 h, l; split_hl(v, h, l);
        long long o = (long long)(c0 + threadIdx.y + dy) * R + r0 + threadIdx.x;
        oh[o] = h; ol[o] = l;
    }
}

// softmax over 4096 fp32, writes bf16 hi/lo in place (row -> 8192 bf16: hi|lo)
__global__ void __launch_bounds__(256) softmax_k(float* __restrict__ S)
{
    const long long row = blockIdx.x;
    const float* p = S + row * (long long)SEQ;
    __nv_bfloat16* ph = reinterpret_cast<__nv_bfloat16*>(S) + row * (long long)(2*SEQ);
    const int tid = threadIdx.x, lane = tid & 31, warp = tid >> 5;
    __shared__ float red[8];

    float v[16];
    float mx = -1e30f;
#pragma unroll
    for (int i = 0; i < 16; i++) { v[i] = p[i*256 + tid]; mx = fmaxf(mx, v[i]); }
#pragma unroll
    for (int o = 16; o > 0; o >>= 1) mx = fmaxf(mx, __shfl_xor_sync(0xffffffffu, mx, o));
    if (!lane) red[warp] = mx;
    __syncthreads();
    mx = red[0];
#pragma unroll
    for (int w = 1; w < 8; w++) mx = fmaxf(mx, red[w]);
    __syncthreads();
    float sm = 0.f;
#pragma unroll
    for (int i = 0; i < 16; i++) { v[i] = __expf(v[i] - mx); sm += v[i]; }
#pragma unroll
    for (int o = 16; o > 0; o >>= 1) sm += __shfl_xor_sync(0xffffffffu, sm, o);
    if (!lane) red[warp] = sm;
    __syncthreads();
    float inv = __frcp_rn(red[0]+red[1]+red[2]+red[3]+red[4]+red[5]+red[6]+red[7]);
#pragma unroll
    for (int i = 0; i < 16; i++) {
        __nv_bfloat16 h, l; split_hl(v[i] * inv, h, l);
        ph[i*256 + tid]       = h;
        ph[SEQ + i*256 + tid] = l;
    }
}

// out = LN(X+U); optionally bf16 hi/lo too
template<bool HL>
__global__ void __launch_bounds__(128) add_ln_k(
    const float* __restrict__ X, const float* __restrict__ U,
    const float* __restrict__ g, const float* __restrict__ b,
    float* __restrict__ outF, __nv_bfloat16* __restrict__ outH, __nv_bfloat16* __restrict__ outL)
{
    const long long row = blockIdx.x;
    const int tid = threadIdx.x, lane = tid & 31, warp = tid >> 5;
    __shared__ float red[4];

    float4 xv = reinterpret_cast<const float4*>(X + row * DMODEL)[tid];
    float4 uv = reinterpret_cast<const float4*>(U + row * DMODEL)[tid];
    float4 s = make_float4(xv.x+uv.x, xv.y+uv.y, xv.z+uv.z, xv.w+uv.w);

    float pp = s.x + s.y + s.z + s.w;
#pragma unroll
    for (int o = 16; o > 0; o >>= 1) pp += __shfl_xor_sync(0xffffffffu, pp, o);
    if (!lane) red[warp] = pp;
    __syncthreads();
    float mu = (red[0]+red[1]+red[2]+red[3]) * (1.f/DMODEL);
    __syncthreads();
    float dx = s.x-mu, dy = s.y-mu, dz = s.z-mu, dw = s.w-mu;
    pp = dx*dx + dy*dy + dz*dz + dw*dw;
#pragma unroll
    for (int o = 16; o > 0; o >>= 1) pp += __shfl_xor_sync(0xffffffffu, pp, o);
    if (!lane) red[warp] = pp;
    __syncthreads();
    float inv = rsqrtf((red[0]+red[1]+red[2]+red[3]) * (1.f/DMODEL) + 1e-5f);

    float4 gv = reinterpret_cast<const float4*>(g)[tid];
    float4 bv = reinterpret_cast<const float4*>(b)[tid];
    float4 o4;
    o4.x = dx*inv*gv.x + bv.x;
    o4.y = dy*inv*gv.y + bv.y;
    o4.z = dz*inv*gv.z + bv.z;
    o4.w = dw*inv*gv.w + bv.w;
    reinterpret_cast<float4*>(outF + row * DMODEL)[tid] = o4;
    if (HL) {
        __nv_bfloat16 h0,l0,h1,l1,h2,l2,h3,l3;
        split_hl(o4.x,h0,l0); split_hl(o4.y,h1,l1);
        split_hl(o4.z,h2,l2); split_hl(o4.w,h3,l3);
        reinterpret_cast<uint2*>(outH + row * DMODEL)[tid] = make_uint2(pack2(h0,h1), pack2(h2,h3));
        reinterpret_cast<uint2*>(outL + row * DMODEL)[tid] = make_uint2(pack2(l0,l1), pack2(l2,l3));
    }
}

// ---------------------------------------------------------------------------
extern "C" void kernel_launch(void* const* d_in, const int* in_sizes, int n_in,
                              void* d_out, int out_size)
{
    (void)in_sizes; (void)n_in; (void)out_size;
    const float* x     = (const float*)d_in[0];
    const float* Wq_w  = (const float*)d_in[1];
    const float* Wq_b  = (const float*)d_in[2];
    const float* Wk_w  = (const float*)d_in[3];
    const float* Wk_b  = (const float*)d_in[4];
    const float* Wv_w  = (const float*)d_in[5];
    const float* Wv_b  = (const float*)d_in[6];
    const float* Wu_w  = (const float*)d_in[7];
    const float* Wu_b  = (const float*)d_in[8];
    const float* ln1_g = (const float*)d_in[9];
    const float* ln1_b = (const float*)d_in[10];
    const float* ff1_w = (const float*)d_in[11];
    const float* ff1_b = (const float*)d_in[12];
    const float* ff2_w = (const float*)d_in[13];
    const float* ff2_b = (const float*)d_in[14];
    const float* ln2_g = (const float*)d_in[15];
    const float* ln2_b = (const float*)d_in[16];
    float* out = (float*)d_out;

#define SYM(T, n, s) T* n; { void* p_; cudaGetSymbolAddress(&p_, s); n = (T*)p_; }
    SYM(float, s, g_s) SYM(float, vf, g_vf) SYM(float, u, g_u) SYM(float, h, g_h)
    SYM(__nv_bfloat16, xh, g_xh) SYM(__nv_bfloat16, xl, g_xl)
    SYM(__nv_bfloat16, qh, g_qh) SYM(__nv_bfloat16, ql, g_ql)
    SYM(__nv_bfloat16, kh, g_kh) SYM(__nv_bfloat16, kl, g_kl)
    SYM(__nv_bfloat16, vth, g_vth) SYM(__nv_bfloat16, vtl, g_vtl)
    SYM(__nv_bfloat16, ah, g_ah) SYM(__nv_bfloat16, al, g_al)
    SYM(__nv_bfloat16, hh, g_hh) SYM(__nv_bfloat16, hl, g_hl)
    SYM(__nv_bfloat16, fh, g_fh) SYM(__nv_bfloat16, fl, g_fl)
    SYM(__nv_bfloat16, wqh, g_wqh) SYM(__nv_bfloat16, wql, g_wql)
    SYM(__nv_bfloat16, wkh, g_wkh) SYM(__nv_bfloat16, wkl, g_wkl)
    SYM(__nv_bfloat16, wvh, g_wvh) SYM(__nv_bfloat16, wvl, g_wvl)
    SYM(__nv_bfloat16, wuh, g_wuh) SYM(__nv_bfloat16, wul, g_wul)
    SYM(__nv_bfloat16, f1h, g_f1h) SYM(__nv_bfloat16, f1l, g_f1l)
    SYM(__nv_bfloat16, f2h, g_f2h) SYM(__nv_bfloat16, f2l, g_f2l)
#undef SYM

    const long long QS = (long long)SEQ * DMODEL;
    const long long SS = (long long)SEQ * SEQ;

    // x -> hi/lo; weights -> K-major hi/lo
    conv_hl<<<(MTOT*DMODEL/4 + 255)/256, 256>>>(x, xh, xl, MTOT*DMODEL/4);
    tconv<<<dim3(16,16,1), dim3(32,8)>>>(Wq_w, 0, wqh, wql, 0, DMODEL, DMODEL);
    tconv<<<dim3(16,16,1), dim3(32,8)>>>(Wk_w, 0, wkh, wkl, 0, DMODEL, DMODEL);
    tconv<<<dim3(16,16,1), dim3(32,8)>>>(Wv_w, 0, wvh, wvl, 0, DMODEL, DMODEL);
    tconv<<<dim3(16,16,1), dim3(32,8)>>>(Wu_w, 0, wuh, wul, 0, DMODEL, DMODEL);
    tconv<<<dim3(FFDIM/32,16,1), dim3(32,8)>>>(ff1_w, 0, f1h, f1l, 0, DMODEL, FFDIM);
    tconv<<<dim3(16,FFDIM/32,1), dim3(32,8)>>>(ff2_w, 0, f2h, f2l, 0, FFDIM, DMODEL);

    // Q, K (hi/lo out), V (fp32 out)
    mma_gemm<false><<<dim3(4,128,1), 256>>>(
        xh, xl, DMODEL, 0, wqh, wql, DMODEL, 0, Wq_b, 1.f, nullptr, qh, ql, DMODEL, 0, DMODEL);
    mma_gemm<false><<<dim3(4,128,1), 256>>>(
        xh, xl, DMODEL, 0, wkh, wkl, DMODEL, 0, Wk_b, 1.f, nullptr, kh, kl, DMODEL, 0, DMODEL);
    mma_gemm<false><<<dim3(4,128,1), 256>>>(
        xh, xl, DMODEL, 0, wvh, wvl, DMODEL, 0, Wv_b, 1.f, vf, nullptr, nullptr, DMODEL, 0, DMODEL);

    // scores = QK^T/8 (fp32)
    mma_gemm<false><<<dim3(SEQ/BNT, SEQ/BMT, BATCH), 256>>>(
        qh, ql, DMODEL, QS, kh, kl, DMODEL, QS, nullptr, 0.125f, s, nullptr, nullptr, SEQ, SS, DMODEL);

    // softmax -> P hi/lo in place
    softmax_k<<<MTOT, 256>>>(s);

    // V^T hi/lo per batch
    tconv<<<dim3(DMODEL/32, SEQ/32, BATCH), dim3(32,8)>>>(vf, QS, vth, vtl, QS, SEQ, DMODEL);

    // attn = P @ V  (A = P hi/lo at lda 8192; B = V^T)
    mma_gemm<false><<<dim3(DMODEL/BNT, SEQ/BMT, BATCH), 256>>>(
        (__nv_bfloat16*)s, (__nv_bfloat16*)s + SEQ, 2*SEQ, (long long)SEQ*2*SEQ,
        vth, vtl, SEQ, QS, nullptr, 1.f, nullptr, ah, al, DMODEL, QS, SEQ);

    // unify
    mma_gemm<false><<<dim3(4,128,1), 256>>>(
        ah, al, DMODEL, 0, wuh, wul, DMODEL, 0, Wu_b, 1.f, u, nullptr, nullptr, DMODEL, 0, DMODEL);

    // h = LN1(x+u), fp32 + hi/lo
    add_ln_k<true><<<MTOT, 128>>>(x, u, ln1_g, ln1_b, h, hh, hl);

    // ff1 (relu, hi/lo out), ff2 (fp32 out)
    mma_gemm<true><<<dim3(FFDIM/BNT,128,1), 256>>>(
        hh, hl, DMODEL, 0, f1h, f1l, DMODEL, 0, ff1_b, 1.f, nullptr, fh, fl, FFDIM, 0, DMODEL);
    mma_gemm<false><<<dim3(4,128,1), 256>>>(
        fh, fl, FFDIM, 0, f2h, f2l, FFDIM, 0, ff2_b, 1.f, u, nullptr, nullptr, DMODEL, 0, FFDIM);

    // out = LN2(h + ffwd)
    add_ln_k<false><<<MTOT, 128>>>(h, u, ln2_g, ln2_b, out, nullptr, nullptr);
}

// round 10
// speedup vs baseline: 3.8162x; 1.4215x over previous
#include <cuda_runtime.h>
#include <cuda_fp16.h>
#include <cstdint>

#define SEQ     4096
#define BATCH   4
#define DMODEL  512
#define FFDIM   2048
#define MTOT    (BATCH*SEQ)

// GEMM tile config (HMMA mma.sync path; target sm_103 has no tcgen05)
#define BMT 128
#define BNT 128
#define NST 3
#define ASZ 8192              // 128 rows * 64B (32 fp16)
#define STG (2*ASZ)           // A + B per stage

// ---------------- scratch ----------------
__device__ __align__(256) float  g_s  [(size_t)BATCH*SEQ*SEQ];
__device__ __align__(256) __half g_xh [(size_t)MTOT*DMODEL];
__device__ __align__(256) __half g_qh [(size_t)MTOT*DMODEL];
__device__ __align__(256) __half g_kh [(size_t)MTOT*DMODEL], g_kl [(size_t)MTOT*DMODEL];
__device__ __align__(256) float  g_vf [(size_t)MTOT*DMODEL];
__device__ __align__(256) __half g_vth[(size_t)MTOT*DMODEL], g_vtl[(size_t)MTOT*DMODEL];
__device__ __align__(256) __half g_ah [(size_t)MTOT*DMODEL];
__device__ __align__(256) float  g_u  [(size_t)MTOT*DMODEL];
__device__ __align__(256) float  g_h  [(size_t)MTOT*DMODEL];
__device__ __align__(256) __half g_hh [(size_t)MTOT*DMODEL];
__device__ __align__(256) __half g_fh [(size_t)MTOT*FFDIM];
__device__ __align__(256) __half g_wqh[DMODEL*DMODEL], g_wql[DMODEL*DMODEL];
__device__ __align__(256) __half g_wkh[DMODEL*DMODEL], g_wkl[DMODEL*DMODEL];
__device__ __align__(256) __half g_wvh[DMODEL*DMODEL], g_wvl[DMODEL*DMODEL];
__device__ __align__(256) __half g_wuh[DMODEL*DMODEL], g_wul[DMODEL*DMODEL];
__device__ __align__(256) __half g_f1h[FFDIM*DMODEL],  g_f1l[FFDIM*DMODEL];
__device__ __align__(256) __half g_f2h[DMODEL*FFDIM],  g_f2l[DMODEL*FFDIM];

// ---------------- PTX helpers (all sm_80+ base-target legal) ----------------
static __device__ __forceinline__ uint32_t smem_u32(const void* p) {
    uint32_t a;
    asm("{ .reg .u64 t; cvta.to.shared.u64 t, %1; cvt.u32.u64 %0, t; }" : "=r"(a) : "l"(p));
    return a;
}
#define CP_ASYNC16(saddr, gptr) \
    asm volatile("cp.async.cg.shared.global [%0], [%1], 16;" :: "r"(saddr), "l"(gptr) : "memory")
#define CP_COMMIT() asm volatile("cp.async.commit_group;" ::: "memory")
#define CP_WAIT1()  asm volatile("cp.async.wait_group 1;"  ::: "memory")

#define LDSM4(r, addr) \
    asm volatile("ldmatrix.sync.aligned.m8n8.x4.shared.b16 {%0,%1,%2,%3}, [%4];" \
        : "=r"((r)[0]), "=r"((r)[1]), "=r"((r)[2]), "=r"((r)[3]) : "r"(addr))

#define MMA16816(c, a, b) \
    asm volatile("mma.sync.aligned.m16n8k16.row.col.f32.f16.f16.f32 " \
        "{%0,%1,%2,%3}, {%4,%5,%6,%7}, {%8,%9}, {%0,%1,%2,%3};" \
        : "+f"((c)[0]), "+f"((c)[1]), "+f"((c)[2]), "+f"((c)[3]) \
        : "r"((a)[0]), "r"((a)[1]), "r"((a)[2]), "r"((a)[3]), "r"((b)[0]), "r"((b)[1]))

static __device__ __forceinline__ void split_hl(float v, __half& h, __half& l) {
    h = __float2half_rn(v);
    l = __float2half_rn(v - __half2float(h));
}
static __device__ __forceinline__ uint32_t pack2(__half a, __half b) {
    return (uint32_t)__half_as_ushort(a) | ((uint32_t)__half_as_ushort(b) << 16);
}

// ---------------------------------------------------------------------------
// HMMA GEMM, fp16 split, 2-phase: C ~= Ah*Bh + Ah*Bl (Al*B dropped, ~2^-11 rel).
// A:[M,K] K-major (lda) hi only. B:[N,K] K-major (ldb) hi+lo.
// D = alpha*sum + bias; outputs fp32 and/or fp16 hi (+lo) (ld=N_).
// CTA 128x128, BK=32, 3-stage cp.async, 8 warps (2M x 4N), warp tile 64x32.
// ---------------------------------------------------------------------------
template<bool RELU>
__global__ void __launch_bounds__(256, 2) mma_gemm(
    const __half* __restrict__ Ahi, long long lda, long long sAz,
    const __half* __restrict__ Bhi, const __half* __restrict__ Blo,
    long long ldb, long long sBz,
    const float* __restrict__ bias, float alpha,
    float* __restrict__ outF, __half* __restrict__ outHi, __half* __restrict__ outLo,
    int N_, long long sCz, int K)
{
    __shared__ __align__(1024) char smem[NST*STG];
    const uint32_t sbase = smem_u32(smem);
    const int tid  = threadIdx.x;
    const int lane = tid & 31;
    const int wid  = tid >> 5;
    const int warp_m = (wid & 1) * 64;
    const int warp_n = (wid >> 1) * 32;

    const long long z    = blockIdx.z;
    const long long arow = (long long)blockIdx.y * BMT;
    const long long brow = (long long)blockIdx.x * BNT;

    const __half* Ahi_z = Ahi + z * sAz;
    const __half* Bhi_z = Bhi + z * sBz;
    const __half* Blo_z = Blo + z * sBz;

    float acc[4][4][4];
#pragma unroll
    for (int i = 0; i < 4; i++)
#pragma unroll
        for (int j = 0; j < 4; j++)
#pragma unroll
            for (int q = 0; q < 4; q++) acc[i][j][q] = 0.f;

    const int r0 = tid >> 2,         c0 = tid & 3;
    const int r1 = (tid + 256) >> 2, c1 = (tid + 256) & 3;
    const uint32_t sw0 = r0*64 + (((c0 ^ ((r0 >> 1) & 3)) << 4));
    const uint32_t sw1 = r1*64 + (((c1 ^ ((r1 >> 1) & 3)) << 4));
    const long long gA0 = (arow + r0) * lda + c0*8;
    const long long gA1 = (arow + r1) * lda + c1*8;
    const long long gB0 = (brow + r0) * ldb + c0*8;
    const long long gB1 = (brow + r1) * ldb + c1*8;

    const int kcPer = K >> 5;
    const int nch   = 2 * kcPer;     // 2 phases: Ah*Bh, Ah*Bl

#define ISSUE(ch) { \
        const int st_ = (ch) % NST; \
        const int ph_ = (ch) / kcPer; \
        const long long kof_ = (long long)((ch) - ph_*kcPer) * 32; \
        const __half* Bp_ = ph_ ? Blo_z : Bhi_z; \
        const uint32_t sA_ = sbase + st_*STG; \
        const uint32_t sB_ = sA_ + ASZ; \
        CP_ASYNC16(sA_ + sw0, Ahi_z + gA0 + kof_); \
        CP_ASYNC16(sA_ + sw1, Ahi_z + gA1 + kof_); \
        CP_ASYNC16(sB_ + sw0, Bp_ + gB0 + kof_); \
        CP_ASYNC16(sB_ + sw1, Bp_ + gB1 + kof_); }

    ISSUE(0); CP_COMMIT();
    ISSUE(1); CP_COMMIT();

    const int rA   = lane & 15;
    const int kcA  = lane >> 4;
    const int swzA = (rA >> 1) & 3;
    const uint32_t aBase = (uint32_t)(warp_m + rA) * 64;
    const int rB   = ((lane >> 4) << 3) + (lane & 7);
    const int kcB  = (lane >> 3) & 1;
    const int swzB = (rB >> 1) & 3;
    const uint32_t bBase = (uint32_t)(warp_n + rB) * 64;

#pragma unroll 1
    for (int j = 0; j < nch; j++) {
        CP_WAIT1();
        __syncthreads();
        if (j + 2 < nch) { ISSUE(j + 2); }
        CP_COMMIT();

        const uint32_t sA = sbase + (j % NST) * STG;
        const uint32_t sB = sA + ASZ;
#pragma unroll
        for (int ks = 0; ks < 2; ks++) {
            uint32_t af[4][4];
            uint32_t bf[4][2];
#pragma unroll
            for (int mt = 0; mt < 4; mt++) {
                uint32_t addr = sA + aBase + mt*1024 + ((uint32_t)((ks*2 + kcA) ^ swzA) << 4);
                LDSM4(af[mt], addr);
            }
#pragma unroll
            for (int nt2 = 0; nt2 < 2; nt2++) {
                uint32_t r[4];
                uint32_t addr = sB + bBase + nt2*1024 + ((uint32_t)((ks*2 + kcB) ^ swzB) << 4);
                LDSM4(r, addr);
                bf[2*nt2][0]   = r[0]; bf[2*nt2][1]   = r[1];
                bf[2*nt2+1][0] = r[2]; bf[2*nt2+1][1] = r[3];
            }
#pragma unroll
            for (int mt = 0; mt < 4; mt++)
#pragma unroll
                for (int nt = 0; nt < 4; nt++)
                    MMA16816(acc[mt][nt], af[mt], bf[nt]);
        }
    }
#undef ISSUE

    // -------- epilogue --------
    const long long mBase = arow + warp_m + (lane >> 2);
    const int       nBase = (int)brow + warp_n + (lane & 3) * 2;
    const long long czB   = z * sCz;
#pragma unroll
    for (int mt = 0; mt < 4; mt++) {
        const long long ra = mBase + mt*16;
        const long long rb = ra + 8;
#pragma unroll
        for (int nt = 0; nt < 4; nt++) {
            const int col = nBase + nt*8;
            float v0 = acc[mt][nt][0] * alpha;
            float v1 = acc[mt][nt][1] * alpha;
            float v2 = acc[mt][nt][2] * alpha;
            float v3 = acc[mt][nt][3] * alpha;
            if (bias) {
                float2 bb = *reinterpret_cast<const float2*>(bias + col);
                v0 += bb.x; v1 += bb.y; v2 += bb.x; v3 += bb.y;
            }
            if (RELU) {
                v0 = fmaxf(v0, 0.f); v1 = fmaxf(v1, 0.f);
                v2 = fmaxf(v2, 0.f); v3 = fmaxf(v3, 0.f);
            }
            if (outF) {
                *reinterpret_cast<float2*>(outF + czB + ra*N_ + col) = make_float2(v0, v1);
                *reinterpret_cast<float2*>(outF + czB + rb*N_ + col) = make_float2(v2, v3);
            }
            if (outHi) {
                __half h0,l0,h1,l1,h2,l2,h3,l3;
                split_hl(v0,h0,l0); split_hl(v1,h1,l1);
                split_hl(v2,h2,l2); split_hl(v3,h3,l3);
                *reinterpret_cast<uint32_t*>(outHi + czB + ra*N_ + col) = pack2(h0, h1);
                *reinterpret_cast<uint32_t*>(outHi + czB + rb*N_ + col) = pack2(h2, h3);
                if (outLo) {
                    *reinterpret_cast<uint32_t*>(outLo + czB + ra*N_ + col) = pack2(l0, l1);
                    *reinterpret_cast<uint32_t*>(outLo + czB + rb*N_ + col) = pack2(l2, l3);
                }
            }
        }
    }
}

// fp32 -> fp16 hi only, elementwise
__global__ void __launch_bounds__(256) conv_h(
    const float* __restrict__ in, __half* __restrict__ oh, int n4)
{
    int i = blockIdx.x * 256 + threadIdx.x;
    if (i >= n4) return;
    float4 v = reinterpret_cast<const float4*>(in)[i];
    reinterpret_cast<uint2*>(oh)[i] = make_uint2(
        pack2(__float2half_rn(v.x), __float2half_rn(v.y)),
        pack2(__float2half_rn(v.z), __float2half_rn(v.w)));
}

// transpose + hi/lo: in fp32 [R,C] -> out fp16 [C,R]
__global__ void tconv(
    const float* __restrict__ in, long long sIn,
    __half* __restrict__ oh, __half* __restrict__ ol, long long sOut,
    int R, int C)
{
    __shared__ float t[32][33];
    const int c0 = blockIdx.x * 32, r0 = blockIdx.y * 32;
    in += blockIdx.z * sIn; oh += blockIdx.z * sOut; ol += blockIdx.z * sOut;
#pragma unroll
    for (int dy = 0; dy < 32; dy += 8)
        t[threadIdx.y + dy][threadIdx.x] =
            in[(long long)(r0 + threadIdx.y + dy) * C + c0 + threadIdx.x];
    __syncthreads();
#pragma unroll
    for (int dy = 0; dy < 32; dy += 8) {
        float v = t[threadIdx.x][threadIdx.y + dy];
        __half h, l; split_hl(v, h, l);
        long long o = (long long)(c0 + threadIdx.y + dy) * R + r0 + threadIdx.x;
        oh[o] = h; ol[o] = l;
    }
}

// softmax over 4096 fp32, writes fp16 hi in place (row stride 2*SEQ halves)
__global__ void __launch_bounds__(256) softmax_k(float* __restrict__ S)
{
    const long long row = blockIdx.x;
    const float* p = S + row * (long long)SEQ;
    __half* ph = reinterpret_cast<__half*>(S) + row * (long long)(2*SEQ);
    const int tid = threadIdx.x, lane = tid & 31, warp = tid >> 5;
    __shared__ float red[8];

    float v[16];
    float mx = -1e30f;
#pragma unroll
    for (int i = 0; i < 16; i++) { v[i] = p[i*256 + tid]; mx = fmaxf(mx, v[i]); }
#pragma unroll
    for (int o = 16; o > 0; o >>= 1) mx = fmaxf(mx, __shfl_xor_sync(0xffffffffu, mx, o));
    if (!lane) red[warp] = mx;
    __syncthreads();
    mx = red[0];
#pragma unroll
    for (int w = 1; w < 8; w++) mx = fmaxf(mx, red[w]);
    __syncthreads();
    float sm = 0.f;
#pragma unroll
    for (int i = 0; i < 16; i++) { v[i] = __expf(v[i] - mx); sm += v[i]; }
#pragma unroll
    for (int o = 16; o > 0; o >>= 1) sm += __shfl_xor_sync(0xffffffffu, sm, o);
    if (!lane) red[warp] = sm;
    __syncthreads();
    float inv = __frcp_rn(red[0]+red[1]+red[2]+red[3]+red[4]+red[5]+red[6]+red[7]);
#pragma unroll
    for (int i = 0; i < 16; i++)
        ph[i*256 + tid] = __float2half_rn(v[i] * inv);
}

// out = LN(X+U); optionally fp16 hi too
template<bool HL>
__global__ void __launch_bounds__(128) add_ln_k(
    const float* __restrict__ X, const float* __restrict__ U,
    const float* __restrict__ g, const float* __restrict__ b,
    float* __restrict__ outF, __half* __restrict__ outH)
{
    const long long row = blockIdx.x;
    const int tid = threadIdx.x, lane = tid & 31, warp = tid >> 5;
    __shared__ float red[4];

    float4 xv = reinterpret_cast<const float4*>(X + row * DMODEL)[tid];
    float4 uv = reinterpret_cast<const float4*>(U + row * DMODEL)[tid];
    float4 s = make_float4(xv.x+uv.x, xv.y+uv.y, xv.z+uv.z, xv.w+uv.w);

    float pp = s.x + s.y + s.z + s.w;
#pragma unroll
    for (int o = 16; o > 0; o >>= 1) pp += __shfl_xor_sync(0xffffffffu, pp, o);
    if (!lane) red[warp] = pp;
    __syncthreads();
    float mu = (red[0]+red[1]+red[2]+red[3]) * (1.f/DMODEL);
    __syncthreads();
    float dx = s.x-mu, dy = s.y-mu, dz = s.z-mu, dw = s.w-mu;
    pp = dx*dx + dy*dy + dz*dz + dw*dw;
#pragma unroll
    for (int o = 16; o > 0; o >>= 1) pp += __shfl_xor_sync(0xffffffffu, pp, o);
    if (!lane) red[warp] = pp;
    __syncthreads();
    float inv = rsqrtf((red[0]+red[1]+red[2]+red[3]) * (1.f/DMODEL) + 1e-5f);

    float4 gv = reinterpret_cast<const float4*>(g)[tid];
    float4 bv = reinterpret_cast<const float4*>(b)[tid];
    float4 o4;
    o4.x = dx*inv*gv.x + bv.x;
    o4.y = dy*inv*gv.y + bv.y;
    o4.z = dz*inv*gv.z + bv.z;
    o4.w = dw*inv*gv.w + bv.w;
    reinterpret_cast<float4*>(outF + row * DMODEL)[tid] = o4;
    if (HL) {
        reinterpret_cast<uint2*>(outH + row * DMODEL)[tid] = make_uint2(
            pack2(__float2half_rn(o4.x), __float2half_rn(o4.y)),
            pack2(__float2half_rn(o4.z), __float2half_rn(o4.w)));
    }
}

// ---------------------------------------------------------------------------
extern "C" void kernel_launch(void* const* d_in, const int* in_sizes, int n_in,
                              void* d_out, int out_size)
{
    (void)in_sizes; (void)n_in; (void)out_size;
    const float* x     = (const float*)d_in[0];
    const float* Wq_w  = (const float*)d_in[1];
    const float* Wq_b  = (const float*)d_in[2];
    const float* Wk_w  = (const float*)d_in[3];
    const float* Wk_b  = (const float*)d_in[4];
    const float* Wv_w  = (const float*)d_in[5];
    const float* Wv_b  = (const float*)d_in[6];
    const float* Wu_w  = (const float*)d_in[7];
    const float* Wu_b  = (const float*)d_in[8];
    const float* ln1_g = (const float*)d_in[9];
    const float* ln1_b = (const float*)d_in[10];
    const float* ff1_w = (const float*)d_in[11];
    const float* ff1_b = (const float*)d_in[12];
    const float* ff2_w = (const float*)d_in[13];
    const float* ff2_b = (const float*)d_in[14];
    const float* ln2_g = (const float*)d_in[15];
    const float* ln2_b = (const float*)d_in[16];
    float* out = (float*)d_out;

#define SYM(T, n, s) T* n; { void* p_; cudaGetSymbolAddress(&p_, s); n = (T*)p_; }
    SYM(float, s, g_s) SYM(float, vf, g_vf) SYM(float, u, g_u) SYM(float, h, g_h)
    SYM(__half, xh, g_xh)
    SYM(__half, qh, g_qh)
    SYM(__half, kh, g_kh) SYM(__half, kl, g_kl)
    SYM(__half, vth, g_vth) SYM(__half, vtl, g_vtl)
    SYM(__half, ah, g_ah)
    SYM(__half, hh, g_hh)
    SYM(__half, fh, g_fh)
    SYM(__half, wqh, g_wqh) SYM(__half, wql, g_wql)
    SYM(__half, wkh, g_wkh) SYM(__half, wkl, g_wkl)
    SYM(__half, wvh, g_wvh) SYM(__half, wvl, g_wvl)
    SYM(__half, wuh, g_wuh) SYM(__half, wul, g_wul)
    SYM(__half, f1h, g_f1h) SYM(__half, f1l, g_f1l)
    SYM(__half, f2h, g_f2h) SYM(__half, f2l, g_f2l)
#undef SYM

    const long long QS = (long long)SEQ * DMODEL;
    const long long SS = (long long)SEQ * SEQ;

    // x -> fp16 hi; weights -> K-major fp16 hi/lo
    conv_h<<<(MTOT*DMODEL/4 + 255)/256, 256>>>(x, xh, MTOT*DMODEL/4);
    tconv<<<dim3(16,16,1), dim3(32,8)>>>(Wq_w, 0, wqh, wql, 0, DMODEL, DMODEL);
    tconv<<<dim3(16,16,1), dim3(32,8)>>>(Wk_w, 0, wkh, wkl, 0, DMODEL, DMODEL);
    tconv<<<dim3(16,16,1), dim3(32,8)>>>(Wv_w, 0, wvh, wvl, 0, DMODEL, DMODEL);
    tconv<<<dim3(16,16,1), dim3(32,8)>>>(Wu_w, 0, wuh, wul, 0, DMODEL, DMODEL);
    tconv<<<dim3(FFDIM/32,16,1), dim3(32,8)>>>(ff1_w, 0, f1h, f1l, 0, DMODEL, FFDIM);
    tconv<<<dim3(16,FFDIM/32,1), dim3(32,8)>>>(ff2_w, 0, f2h, f2l, 0, FFDIM, DMODEL);

    // Q (hi out), K (hi+lo out), V (fp32 out)
    mma_gemm<false><<<dim3(4,128,1), 256>>>(
        xh, DMODEL, 0, wqh, wql, DMODEL, 0, Wq_b, 1.f, nullptr, qh, nullptr, DMODEL, 0, DMODEL);
    mma_gemm<false><<<dim3(4,128,1), 256>>>(
        xh, DMODEL, 0, wkh, wkl, DMODEL, 0, Wk_b, 1.f, nullptr, kh, kl, DMODEL, 0, DMODEL);
    mma_gemm<false><<<dim3(4,128,1), 256>>>(
        xh, DMODEL, 0, wvh, wvl, DMODEL, 0, Wv_b, 1.f, vf, nullptr, nullptr, DMODEL, 0, DMODEL);

    // scores = QK^T/8 (fp32)
    mma_gemm<false><<<dim3(SEQ/BNT, SEQ/BMT, BATCH), 256>>>(
        qh, DMODEL, QS, kh, kl, DMODEL, QS, nullptr, 0.125f, s, nullptr, nullptr, SEQ, SS, DMODEL);

    // softmax -> P fp16 hi in place
    softmax_k<<<MTOT, 256>>>(s);

    // V^T hi/lo per batch
    tconv<<<dim3(DMODEL/32, SEQ/32, BATCH), dim3(32,8)>>>(vf, QS, vth, vtl, QS, SEQ, DMODEL);

    // attn = P @ V  (A = P fp16 hi at lda 2*SEQ; B = V^T hi/lo)
    mma_gemm<false><<<dim3(DMODEL/BNT, SEQ/BMT, BATCH), 256>>>(
        (const __half*)s, 2*SEQ, (long long)SEQ*2*SEQ,
        vth, vtl, SEQ, QS, nullptr, 1.f, nullptr, ah, nullptr, DMODEL, QS, SEQ);

    // unify
    mma_gemm<false><<<dim3(4,128,1), 256>>>(
        ah, DMODEL, 0, wuh, wul, DMODEL, 0, Wu_b, 1.f, u, nullptr, nullptr, DMODEL, 0, DMODEL);

    // h = LN1(x+u), fp32 + fp16 hi
    add_ln_k<true><<<MTOT, 128>>>(x, u, ln1_g, ln1_b, h, hh);

    // ff1 (relu, hi out), ff2 (fp32 out)
    mma_gemm<true><<<dim3(FFDIM/BNT,128,1), 256>>>(
        hh, DMODEL, 0, f1h, f1l, DMODEL, 0, ff1_b, 1.f, nullptr, fh, nullptr, FFDIM, 0, DMODEL);
    mma_gemm<false><<<dim3(4,128,1), 256>>>(
        fh, FFDIM, 0, f2h, f2l, FFDIM, 0, ff2_b, 1.f, u, nullptr, nullptr, DMODEL, 0, FFDIM);

    // out = LN2(h + ffwd)
    add_ln_k<false><<<MTOT, 128>>>(h, u, ln2_g, ln2_b, out, nullptr);
}

// round 11
// speedup vs baseline: 7.1757x; 1.8804x over previous
#include <cuda_runtime.h>
#include <cuda_fp16.h>
#include <cstdint>

#define SEQ     4096
#define BATCH   4
#define DMODEL  512
#define FFDIM   2048
#define MTOT    (BATCH*SEQ)

// GEMM tile config (HMMA mma.sync path; target sm_103 has no tcgen05)
#define BMT 128
#define BNT 128
#define NST 3
#define ASZ 8192              // 128 rows * 64B (32 fp16)
#define STG (2*ASZ)           // A + B per stage

// ---------------- scratch ----------------
__device__ __align__(256) float  g_s  [(size_t)BATCH*SEQ*SEQ];
__device__ __align__(256) __half g_xh [(size_t)MTOT*DMODEL];
__device__ __align__(256) __half g_qh [(size_t)MTOT*DMODEL];
__device__ __align__(256) __half g_kh [(size_t)MTOT*DMODEL];
__device__ __align__(256) float  g_vf [(size_t)MTOT*DMODEL];
__device__ __align__(256) __half g_vth[(size_t)MTOT*DMODEL];
__device__ __align__(256) __half g_ah [(size_t)MTOT*DMODEL];
__device__ __align__(256) float  g_u  [(size_t)MTOT*DMODEL];
__device__ __align__(256) float  g_h  [(size_t)MTOT*DMODEL];
__device__ __align__(256) __half g_hh [(size_t)MTOT*DMODEL];
__device__ __align__(256) __half g_fh [(size_t)MTOT*FFDIM];
__device__ __align__(256) __half g_wqh[DMODEL*DMODEL];
__device__ __align__(256) __half g_wkh[DMODEL*DMODEL];
__device__ __align__(256) __half g_wvh[DMODEL*DMODEL];
__device__ __align__(256) __half g_wuh[DMODEL*DMODEL];
__device__ __align__(256) __half g_f1h[FFDIM*DMODEL];
__device__ __align__(256) __half g_f2h[DMODEL*FFDIM];

// ---------------- PTX helpers (all sm_80+ base-target legal) ----------------
static __device__ __forceinline__ uint32_t smem_u32(const void* p) {
    uint32_t a;
    asm("{ .reg .u64 t; cvta.to.shared.u64 t, %1; cvt.u32.u64 %0, t; }" : "=r"(a) : "l"(p));
    return a;
}
#define CP_ASYNC16(saddr, gptr) \
    asm volatile("cp.async.cg.shared.global [%0], [%1], 16;" :: "r"(saddr), "l"(gptr) : "memory")
#define CP_COMMIT() asm volatile("cp.async.commit_group;" ::: "memory")
#define CP_WAIT1()  asm volatile("cp.async.wait_group 1;"  ::: "memory")

#define LDSM4(r, addr) \
    asm volatile("ldmatrix.sync.aligned.m8n8.x4.shared.b16 {%0,%1,%2,%3}, [%4];" \
        : "=r"((r)[0]), "=r"((r)[1]), "=r"((r)[2]), "=r"((r)[3]) : "r"(addr))

#define MMA16816(c, a, b) \
    asm volatile("mma.sync.aligned.m16n8k16.row.col.f32.f16.f16.f32 " \
        "{%0,%1,%2,%3}, {%4,%5,%6,%7}, {%8,%9}, {%0,%1,%2,%3};" \
        : "+f"((c)[0]), "+f"((c)[1]), "+f"((c)[2]), "+f"((c)[3]) \
        : "r"((a)[0]), "r"((a)[1]), "r"((a)[2]), "r"((a)[3]), "r"((b)[0]), "r"((b)[1]))

static __device__ __forceinline__ uint32_t pack2(__half a, __half b) {
    return (uint32_t)__half_as_ushort(a) | ((uint32_t)__half_as_ushort(b) << 16);
}

// ---------------------------------------------------------------------------
// HMMA GEMM, single-pass fp16 (rounding error ~1e-4 rel, calibrated R10).
// A:[M,K] K-major (lda). B:[N,K] K-major (ldb).
// D = alpha*A@B^T + bias; outputs fp32 and/or fp16 (ld=N_).
// CTA 128x128, BK=32, 3-stage cp.async, 8 warps (2M x 4N), warp tile 64x32.
// ---------------------------------------------------------------------------
template<bool RELU>
__global__ void __launch_bounds__(256, 2) mma_gemm(
    const __half* __restrict__ A, long long lda, long long sAz,
    const __half* __restrict__ B, long long ldb, long long sBz,
    const float* __restrict__ bias, float alpha,
    float* __restrict__ outF, __half* __restrict__ outH,
    int N_, long long sCz, int K)
{
    __shared__ __align__(1024) char smem[NST*STG];
    const uint32_t sbase = smem_u32(smem);
    const int tid  = threadIdx.x;
    const int lane = tid & 31;
    const int wid  = tid >> 5;
    const int warp_m = (wid & 1) * 64;
    const int warp_n = (wid >> 1) * 32;

    const long long z    = blockIdx.z;
    const long long arow = (long long)blockIdx.y * BMT;
    const long long brow = (long long)blockIdx.x * BNT;

    const __half* A_z = A + z * sAz;
    const __half* B_z = B + z * sBz;

    float acc[4][4][4];
#pragma unroll
    for (int i = 0; i < 4; i++)
#pragma unroll
        for (int j = 0; j < 4; j++)
#pragma unroll
            for (int q = 0; q < 4; q++) acc[i][j][q] = 0.f;

    const int r0 = tid >> 2,         c0 = tid & 3;
    const int r1 = (tid + 256) >> 2, c1 = (tid + 256) & 3;
    const uint32_t sw0 = r0*64 + (((c0 ^ ((r0 >> 1) & 3)) << 4));
    const uint32_t sw1 = r1*64 + (((c1 ^ ((r1 >> 1) & 3)) << 4));
    const long long gA0 = (arow + r0) * lda + c0*8;
    const long long gA1 = (arow + r1) * lda + c1*8;
    const long long gB0 = (brow + r0) * ldb + c0*8;
    const long long gB1 = (brow + r1) * ldb + c1*8;

    const int nch = K >> 5;          // single pass over K

#define ISSUE(ch) { \
        const int st_ = (ch) % NST; \
        const long long kof_ = (long long)(ch) * 32; \
        const uint32_t sA_ = sbase + st_*STG; \
        const uint32_t sB_ = sA_ + ASZ; \
        CP_ASYNC16(sA_ + sw0, A_z + gA0 + kof_); \
        CP_ASYNC16(sA_ + sw1, A_z + gA1 + kof_); \
        CP_ASYNC16(sB_ + sw0, B_z + gB0 + kof_); \
        CP_ASYNC16(sB_ + sw1, B_z + gB1 + kof_); }

    ISSUE(0); CP_COMMIT();
    ISSUE(1); CP_COMMIT();

    const int rA   = lane & 15;
    const int kcA  = lane >> 4;
    const int swzA = (rA >> 1) & 3;
    const uint32_t aBase = (uint32_t)(warp_m + rA) * 64;
    const int rB   = ((lane >> 4) << 3) + (lane & 7);
    const int kcB  = (lane >> 3) & 1;
    const int swzB = (rB >> 1) & 3;
    const uint32_t bBase = (uint32_t)(warp_n + rB) * 64;

#pragma unroll 1
    for (int j = 0; j < nch; j++) {
        CP_WAIT1();
        __syncthreads();
        if (j + 2 < nch) { ISSUE(j + 2); }
        CP_COMMIT();

        const uint32_t sA = sbase + (j % NST) * STG;
        const uint32_t sB = sA + ASZ;
#pragma unroll
        for (int ks = 0; ks < 2; ks++) {
            uint32_t af[4][4];
            uint32_t bf[4][2];
#pragma unroll
            for (int mt = 0; mt < 4; mt++) {
                uint32_t addr = sA + aBase + mt*1024 + ((uint32_t)((ks*2 + kcA) ^ swzA) << 4);
                LDSM4(af[mt], addr);
            }
#pragma unroll
            for (int nt2 = 0; nt2 < 2; nt2++) {
                uint32_t r[4];
                uint32_t addr = sB + bBase + nt2*1024 + ((uint32_t)((ks*2 + kcB) ^ swzB) << 4);
                LDSM4(r, addr);
                bf[2*nt2][0]   = r[0]; bf[2*nt2][1]   = r[1];
                bf[2*nt2+1][0] = r[2]; bf[2*nt2+1][1] = r[3];
            }
#pragma unroll
            for (int mt = 0; mt < 4; mt++)
#pragma unroll
                for (int nt = 0; nt < 4; nt++)
                    MMA16816(acc[mt][nt], af[mt], bf[nt]);
        }
    }
#undef ISSUE

    // -------- epilogue --------
    const long long mBase = arow + warp_m + (lane >> 2);
    const int       nBase = (int)brow + warp_n + (lane & 3) * 2;
    const long long czB   = z * sCz;
#pragma unroll
    for (int mt = 0; mt < 4; mt++) {
        const long long ra = mBase + mt*16;
        const long long rb = ra + 8;
#pragma unroll
        for (int nt = 0; nt < 4; nt++) {
            const int col = nBase + nt*8;
            float v0 = acc[mt][nt][0] * alpha;
            float v1 = acc[mt][nt][1] * alpha;
            float v2 = acc[mt][nt][2] * alpha;
            float v3 = acc[mt][nt][3] * alpha;
            if (bias) {
                float2 bb = *reinterpret_cast<const float2*>(bias + col);
                v0 += bb.x; v1 += bb.y; v2 += bb.x; v3 += bb.y;
            }
            if (RELU) {
                v0 = fmaxf(v0, 0.f); v1 = fmaxf(v1, 0.f);
                v2 = fmaxf(v2, 0.f); v3 = fmaxf(v3, 0.f);
            }
            if (outF) {
                *reinterpret_cast<float2*>(outF + czB + ra*N_ + col) = make_float2(v0, v1);
                *reinterpret_cast<float2*>(outF + czB + rb*N_ + col) = make_float2(v2, v3);
            }
            if (outH) {
                *reinterpret_cast<uint32_t*>(outH + czB + ra*N_ + col) =
                    pack2(__float2half_rn(v0), __float2half_rn(v1));
                *reinterpret_cast<uint32_t*>(outH + czB + rb*N_ + col) =
                    pack2(__float2half_rn(v2), __float2half_rn(v3));
            }
        }
    }
}

// fp32 -> fp16 elementwise
__global__ void __launch_bounds__(256) conv_h(
    const float* __restrict__ in, __half* __restrict__ oh, int n4)
{
    int i = blockIdx.x * 256 + threadIdx.x;
    if (i >= n4) return;
    float4 v = reinterpret_cast<const float4*>(in)[i];
    reinterpret_cast<uint2*>(oh)[i] = make_uint2(
        pack2(__float2half_rn(v.x), __float2half_rn(v.y)),
        pack2(__float2half_rn(v.z), __float2half_rn(v.w)));
}

// transpose + fp16: in fp32 [R,C] -> out fp16 [C,R]
__global__ void tconv(
    const float* __restrict__ in, long long sIn,
    __half* __restrict__ oh, long long sOut,
    int R, int C)
{
    __shared__ float t[32][33];
    const int c0 = blockIdx.x * 32, r0 = blockIdx.y * 32;
    in += blockIdx.z * sIn; oh += blockIdx.z * sOut;
#pragma unroll
    for (int dy = 0; dy < 32; dy += 8)
        t[threadIdx.y + dy][threadIdx.x] =
            in[(long long)(r0 + threadIdx.y + dy) * C + c0 + threadIdx.x];
    __syncthreads();
#pragma unroll
    for (int dy = 0; dy < 32; dy += 8) {
        float v = t[threadIdx.x][threadIdx.y + dy];
        long long o = (long long)(c0 + threadIdx.y + dy) * R + r0 + threadIdx.x;
        oh[o] = __float2half_rn(v);
    }
}

// softmax over 4096 fp32, writes fp16 in place (row stride 2*SEQ halves)
__global__ void __launch_bounds__(256) softmax_k(float* __restrict__ S)
{
    const long long row = blockIdx.x;
    const float* p = S + row * (long long)SEQ;
    __half* ph = reinterpret_cast<__half*>(S) + row * (long long)(2*SEQ);
    const int tid = threadIdx.x, lane = tid & 31, warp = tid >> 5;
    __shared__ float red[8];

    float v[16];
    float mx = -1e30f;
#pragma unroll
    for (int i = 0; i < 16; i++) { v[i] = p[i*256 + tid]; mx = fmaxf(mx, v[i]); }
#pragma unroll
    for (int o = 16; o > 0; o >>= 1) mx = fmaxf(mx, __shfl_xor_sync(0xffffffffu, mx, o));
    if (!lane) red[warp] = mx;
    __syncthreads();
    mx = red[0];
#pragma unroll
    for (int w = 1; w < 8; w++) mx = fmaxf(mx, red[w]);
    __syncthreads();
    float sm = 0.f;
#pragma unroll
    for (int i = 0; i < 16; i++) { v[i] = __expf(v[i] - mx); sm += v[i]; }
#pragma unroll
    for (int o = 16; o > 0; o >>= 1) sm += __shfl_xor_sync(0xffffffffu, sm, o);
    if (!lane) red[warp] = sm;
    __syncthreads();
    float inv = __frcp_rn(red[0]+red[1]+red[2]+red[3]+red[4]+red[5]+red[6]+red[7]);
#pragma unroll
    for (int i = 0; i < 16; i++)
        ph[i*256 + tid] = __float2half_rn(v[i] * inv);
}

// out = LN(X+U); optionally fp16 too
template<bool HL>
__global__ void __launch_bounds__(128) add_ln_k(
    const float* __restrict__ X, const float* __restrict__ U,
    const float* __restrict__ g, const float* __restrict__ b,
    float* __restrict__ outF, __half* __restrict__ outH)
{
    const long long row = blockIdx.x;
    const int tid = threadIdx.x, lane = tid & 31, warp = tid >> 5;
    __shared__ float red[4];

    float4 xv = reinterpret_cast<const float4*>(X + row * DMODEL)[tid];
    float4 uv = reinterpret_cast<const float4*>(U + row * DMODEL)[tid];
    float4 s = make_float4(xv.x+uv.x, xv.y+uv.y, xv.z+uv.z, xv.w+uv.w);

    float pp = s.x + s.y + s.z + s.w;
#pragma unroll
    for (int o = 16; o > 0; o >>= 1) pp += __shfl_xor_sync(0xffffffffu, pp, o);
    if (!lane) red[warp] = pp;
    __syncthreads();
    float mu = (red[0]+red[1]+red[2]+red[3]) * (1.f/DMODEL);
    __syncthreads();
    float dx = s.x-mu, dy = s.y-mu, dz = s.z-mu, dw = s.w-mu;
    pp = dx*dx + dy*dy + dz*dz + dw*dw;
#pragma unroll
    for (int o = 16; o > 0; o >>= 1) pp += __shfl_xor_sync(0xffffffffu, pp, o);
    if (!lane) red[warp] = pp;
    __syncthreads();
    float inv = rsqrtf((red[0]+red[1]+red[2]+red[3]) * (1.f/DMODEL) + 1e-5f);

    float4 gv = reinterpret_cast<const float4*>(g)[tid];
    float4 bv = reinterpret_cast<const float4*>(b)[tid];
    float4 o4;
    o4.x = dx*inv*gv.x + bv.x;
    o4.y = dy*inv*gv.y + bv.y;
    o4.z = dz*inv*gv.z + bv.z;
    o4.w = dw*inv*gv.w + bv.w;
    reinterpret_cast<float4*>(outF + row * DMODEL)[tid] = o4;
    if (HL) {
        reinterpret_cast<uint2*>(outH + row * DMODEL)[tid] = make_uint2(
            pack2(__float2half_rn(o4.x), __float2half_rn(o4.y)),
            pack2(__float2half_rn(o4.z), __float2half_rn(o4.w)));
    }
}

// ---------------------------------------------------------------------------
extern "C" void kernel_launch(void* const* d_in, const int* in_sizes, int n_in,
                              void* d_out, int out_size)
{
    (void)in_sizes; (void)n_in; (void)out_size;
    const float* x     = (const float*)d_in[0];
    const float* Wq_w  = (const float*)d_in[1];
    const float* Wq_b  = (const float*)d_in[2];
    const float* Wk_w  = (const float*)d_in[3];
    const float* Wk_b  = (const float*)d_in[4];
    const float* Wv_w  = (const float*)d_in[5];
    const float* Wv_b  = (const float*)d_in[6];
    const float* Wu_w  = (const float*)d_in[7];
    const float* Wu_b  = (const float*)d_in[8];
    const float* ln1_g = (const float*)d_in[9];
    const float* ln1_b = (const float*)d_in[10];
    const float* ff1_w = (const float*)d_in[11];
    const float* ff1_b = (const float*)d_in[12];
    const float* ff2_w = (const float*)d_in[13];
    const float* ff2_b = (const float*)d_in[14];
    const float* ln2_g = (const float*)d_in[15];
    const float* ln2_b = (const float*)d_in[16];
    float* out = (float*)d_out;

#define SYM(T, n, s) T* n; { void* p_; cudaGetSymbolAddress(&p_, s); n = (T*)p_; }
    SYM(float, s, g_s) SYM(float, vf, g_vf) SYM(float, u, g_u) SYM(float, h, g_h)
    SYM(__half, xh, g_xh)
    SYM(__half, qh, g_qh)
    SYM(__half, kh, g_kh)
    SYM(__half, vth, g_vth)
    SYM(__half, ah, g_ah)
    SYM(__half, hh, g_hh)
    SYM(__half, fh, g_fh)
    SYM(__half, wqh, g_wqh)
    SYM(__half, wkh, g_wkh)
    SYM(__half, wvh, g_wvh)
    SYM(__half, wuh, g_wuh)
    SYM(__half, f1h, g_f1h)
    SYM(__half, f2h, g_f2h)
#undef SYM

    const long long QS = (long long)SEQ * DMODEL;
    const long long SS = (long long)SEQ * SEQ;

    // x -> fp16; weights -> K-major fp16
    conv_h<<<(MTOT*DMODEL/4 + 255)/256, 256>>>(x, xh, MTOT*DMODEL/4);
    tconv<<<dim3(16,16,1), dim3(32,8)>>>(Wq_w, 0, wqh, 0, DMODEL, DMODEL);
    tconv<<<dim3(16,16,1), dim3(32,8)>>>(Wk_w, 0, wkh, 0, DMODEL, DMODEL);
    tconv<<<dim3(16,16,1), dim3(32,8)>>>(Wv_w, 0, wvh, 0, DMODEL, DMODEL);
    tconv<<<dim3(16,16,1), dim3(32,8)>>>(Wu_w, 0, wuh, 0, DMODEL, DMODEL);
    tconv<<<dim3(FFDIM/32,16,1), dim3(32,8)>>>(ff1_w, 0, f1h, 0, DMODEL, FFDIM);
    tconv<<<dim3(16,FFDIM/32,1), dim3(32,8)>>>(ff2_w, 0, f2h, 0, FFDIM, DMODEL);

    // Q, K (fp16 out), V (fp32 out)
    mma_gemm<false><<<dim3(4,128,1), 256>>>(
        xh, DMODEL, 0, wqh, DMODEL, 0, Wq_b, 1.f, nullptr, qh, DMODEL, 0, DMODEL);
    mma_gemm<false><<<dim3(4,128,1), 256>>>(
        xh, DMODEL, 0, wkh, DMODEL, 0, Wk_b, 1.f, nullptr, kh, DMODEL, 0, DMODEL);
    mma_gemm<false><<<dim3(4,128,1), 256>>>(
        xh, DMODEL, 0, wvh, DMODEL, 0, Wv_b, 1.f, vf, nullptr, DMODEL, 0, DMODEL);

    // scores = QK^T/8 (fp32)
    mma_gemm<false><<<dim3(SEQ/BNT, SEQ/BMT, BATCH), 256>>>(
        qh, DMODEL, QS, kh, DMODEL, QS, nullptr, 0.125f, s, nullptr, SEQ, SS, DMODEL);

    // softmax -> P fp16 in place
    softmax_k<<<MTOT, 256>>>(s);

    // V^T per batch
    tconv<<<dim3(DMODEL/32, SEQ/32, BATCH), dim3(32,8)>>>(vf, QS, vth, QS, SEQ, DMODEL);

    // attn = P @ V  (A = P fp16 at lda 2*SEQ; B = V^T)
    mma_gemm<false><<<dim3(DMODEL/BNT, SEQ/BMT, BATCH), 256>>>(
        (const __half*)s, 2*SEQ, (long long)SEQ*2*SEQ,
        vth, SEQ, QS, nullptr, 1.f, nullptr, ah, DMODEL, QS, SEQ);

    // unify
    mma_gemm<false><<<dim3(4,128,1), 256>>>(
        ah, DMODEL, 0, wuh, DMODEL, 0, Wu_b, 1.f, u, nullptr, DMODEL, 0, DMODEL);

    // h = LN1(x+u), fp32 + fp16
    add_ln_k<true><<<MTOT, 128>>>(x, u, ln1_g, ln1_b, h, hh);

    // ff1 (relu, fp16 out), ff2 (fp32 out)
    mma_gemm<true><<<dim3(FFDIM/BNT,128,1), 256>>>(
        hh, DMODEL, 0, f1h, DMODEL, 0, ff1_b, 1.f, nullptr, fh, FFDIM, 0, DMODEL);
    mma_gemm<false><<<dim3(4,128,1), 256>>>(
        fh, FFDIM, 0, f2h, FFDIM, 0, ff2_b, 1.f, u, nullptr, DMODEL, 0, FFDIM);

    // out = LN2(h + ffwd)
    add_ln_k<false><<<MTOT, 128>>>(h, u, ln2_g, ln2_b, out, nullptr);
}

// round 12
// speedup vs baseline: 7.3348x; 1.0222x over previous
#include <cuda_runtime.h>
#include <cuda_fp16.h>
#include <cstdint>

#define SEQ     4096
#define BATCH   4
#define DMODEL  512
#define FFDIM   2048
#define MTOT    (BATCH*SEQ)
#define NQKV    (3*DMODEL)    // 1536

// GEMM tile config (HMMA mma.sync path; target sm_103 has no tcgen05)
#define BMT 128
#define BNT 128
#define NST 3
#define ASZ 8192              // 128 rows * 64B (32 fp16)
#define STG (2*ASZ)           // A + B per stage

// ---------------- scratch ----------------
__device__ __align__(256) __half g_s   [(size_t)BATCH*SEQ*SEQ];     // fp16 scores/probs
__device__ __align__(256) __half g_xh  [(size_t)MTOT*DMODEL];
__device__ __align__(256) __half g_qkv [(size_t)MTOT*NQKV];         // Q|K|V fp16
__device__ __align__(256) __half g_vth [(size_t)MTOT*DMODEL];       // V^T per batch
__device__ __align__(256) __half g_ah  [(size_t)MTOT*DMODEL];
__device__ __align__(256) float  g_u   [(size_t)MTOT*DMODEL];
__device__ __align__(256) float  g_h   [(size_t)MTOT*DMODEL];
__device__ __align__(256) __half g_hh  [(size_t)MTOT*DMODEL];
__device__ __align__(256) __half g_fh  [(size_t)MTOT*FFDIM];
__device__ __align__(256) __half g_wqkv[NQKV*DMODEL];
__device__ __align__(256) float  g_qkvb[NQKV];
__device__ __align__(256) __half g_wuh [DMODEL*DMODEL];
__device__ __align__(256) __half g_f1h [FFDIM*DMODEL];
__device__ __align__(256) __half g_f2h [DMODEL*FFDIM];

// ---------------- PTX helpers (all sm_80+ base-target legal) ----------------
static __device__ __forceinline__ uint32_t smem_u32(const void* p) {
    uint32_t a;
    asm("{ .reg .u64 t; cvta.to.shared.u64 t, %1; cvt.u32.u64 %0, t; }" : "=r"(a) : "l"(p));
    return a;
}
#define CP_ASYNC16(saddr, gptr) \
    asm volatile("cp.async.cg.shared.global [%0], [%1], 16;" :: "r"(saddr), "l"(gptr) : "memory")
#define CP_COMMIT() asm volatile("cp.async.commit_group;" ::: "memory")
#define CP_WAIT1()  asm volatile("cp.async.wait_group 1;"  ::: "memory")

#define LDSM4(r, addr) \
    asm volatile("ldmatrix.sync.aligned.m8n8.x4.shared.b16 {%0,%1,%2,%3}, [%4];" \
        : "=r"((r)[0]), "=r"((r)[1]), "=r"((r)[2]), "=r"((r)[3]) : "r"(addr))

#define MMA16816(c, a, b) \
    asm volatile("mma.sync.aligned.m16n8k16.row.col.f32.f16.f16.f32 " \
        "{%0,%1,%2,%3}, {%4,%5,%6,%7}, {%8,%9}, {%0,%1,%2,%3};" \
        : "+f"((c)[0]), "+f"((c)[1]), "+f"((c)[2]), "+f"((c)[3]) \
        : "r"((a)[0]), "r"((a)[1]), "r"((a)[2]), "r"((a)[3]), "r"((b)[0]), "r"((b)[1]))

static __device__ __forceinline__ uint32_t pack2(__half a, __half b) {
    return (uint32_t)__half_as_ushort(a) | ((uint32_t)__half_as_ushort(b) << 16);
}

// ---------------------------------------------------------------------------
// HMMA GEMM, single-pass fp16. A:[M,K] K-major (lda). B:[N,K] K-major (ldb).
// D = alpha*A@B^T + bias; outputs fp32 and/or fp16 (ld=N_).
// CTA 128x128, BK=32, 3-stage cp.async, 8 warps (2M x 4N), warp tile 64x32.
// ---------------------------------------------------------------------------
template<bool RELU>
__global__ void __launch_bounds__(256, 2) mma_gemm(
    const __half* __restrict__ A, long long lda, long long sAz,
    const __half* __restrict__ B, long long ldb, long long sBz,
    const float* __restrict__ bias, float alpha,
    float* __restrict__ outF, __half* __restrict__ outH,
    int N_, long long sCz, int K)
{
    __shared__ __align__(1024) char smem[NST*STG];
    const uint32_t sbase = smem_u32(smem);
    const int tid  = threadIdx.x;
    const int lane = tid & 31;
    const int wid  = tid >> 5;
    const int warp_m = (wid & 1) * 64;
    const int warp_n = (wid >> 1) * 32;

    const long long z    = blockIdx.z;
    const long long arow = (long long)blockIdx.y * BMT;
    const long long brow = (long long)blockIdx.x * BNT;

    const __half* A_z = A + z * sAz;
    const __half* B_z = B + z * sBz;

    float acc[4][4][4];
#pragma unroll
    for (int i = 0; i < 4; i++)
#pragma unroll
        for (int j = 0; j < 4; j++)
#pragma unroll
            for (int q = 0; q < 4; q++) acc[i][j][q] = 0.f;

    const int r0 = tid >> 2,         c0 = tid & 3;
    const int r1 = (tid + 256) >> 2, c1 = (tid + 256) & 3;
    const uint32_t sw0 = r0*64 + (((c0 ^ ((r0 >> 1) & 3)) << 4));
    const uint32_t sw1 = r1*64 + (((c1 ^ ((r1 >> 1) & 3)) << 4));
    const long long gA0 = (arow + r0) * lda + c0*8;
    const long long gA1 = (arow + r1) * lda + c1*8;
    const long long gB0 = (brow + r0) * ldb + c0*8;
    const long long gB1 = (brow + r1) * ldb + c1*8;

    const int nch = K >> 5;

#define ISSUE(ch) { \
        const int st_ = (ch) % NST; \
        const long long kof_ = (long long)(ch) * 32; \
        const uint32_t sA_ = sbase + st_*STG; \
        const uint32_t sB_ = sA_ + ASZ; \
        CP_ASYNC16(sA_ + sw0, A_z + gA0 + kof_); \
        CP_ASYNC16(sA_ + sw1, A_z + gA1 + kof_); \
        CP_ASYNC16(sB_ + sw0, B_z + gB0 + kof_); \
        CP_ASYNC16(sB_ + sw1, B_z + gB1 + kof_); }

    ISSUE(0); CP_COMMIT();
    ISSUE(1); CP_COMMIT();

    const int rA   = lane & 15;
    const int kcA  = lane >> 4;
    const int swzA = (rA >> 1) & 3;
    const uint32_t aBase = (uint32_t)(warp_m + rA) * 64;
    const int rB   = ((lane >> 4) << 3) + (lane & 7);
    const int kcB  = (lane >> 3) & 1;
    const int swzB = (rB >> 1) & 3;
    const uint32_t bBase = (uint32_t)(warp_n + rB) * 64;

#pragma unroll 1
    for (int j = 0; j < nch; j++) {
        CP_WAIT1();
        __syncthreads();
        if (j + 2 < nch) { ISSUE(j + 2); }
        CP_COMMIT();

        const uint32_t sA = sbase + (j % NST) * STG;
        const uint32_t sB = sA + ASZ;
#pragma unroll
        for (int ks = 0; ks < 2; ks++) {
            uint32_t af[4][4];
            uint32_t bf[4][2];
#pragma unroll
            for (int mt = 0; mt < 4; mt++) {
                uint32_t addr = sA + aBase + mt*1024 + ((uint32_t)((ks*2 + kcA) ^ swzA) << 4);
                LDSM4(af[mt], addr);
            }
#pragma unroll
            for (int nt2 = 0; nt2 < 2; nt2++) {
                uint32_t r[4];
                uint32_t addr = sB + bBase + nt2*1024 + ((uint32_t)((ks*2 + kcB) ^ swzB) << 4);
                LDSM4(r, addr);
                bf[2*nt2][0]   = r[0]; bf[2*nt2][1]   = r[1];
                bf[2*nt2+1][0] = r[2]; bf[2*nt2+1][1] = r[3];
            }
#pragma unroll
            for (int mt = 0; mt < 4; mt++)
#pragma unroll
                for (int nt = 0; nt < 4; nt++)
                    MMA16816(acc[mt][nt], af[mt], bf[nt]);
        }
    }
#undef ISSUE

    // -------- epilogue --------
    const long long mBase = arow + warp_m + (lane >> 2);
    const int       nBase = (int)brow + warp_n + (lane & 3) * 2;
    const long long czB   = z * sCz;
#pragma unroll
    for (int mt = 0; mt < 4; mt++) {
        const long long ra = mBase + mt*16;
        const long long rb = ra + 8;
#pragma unroll
        for (int nt = 0; nt < 4; nt++) {
            const int col = nBase + nt*8;
            float v0 = acc[mt][nt][0] * alpha;
            float v1 = acc[mt][nt][1] * alpha;
            float v2 = acc[mt][nt][2] * alpha;
            float v3 = acc[mt][nt][3] * alpha;
            if (bias) {
                float2 bb = *reinterpret_cast<const float2*>(bias + col);
                v0 += bb.x; v1 += bb.y; v2 += bb.x; v3 += bb.y;
            }
            if (RELU) {
                v0 = fmaxf(v0, 0.f); v1 = fmaxf(v1, 0.f);
                v2 = fmaxf(v2, 0.f); v3 = fmaxf(v3, 0.f);
            }
            if (outF) {
                *reinterpret_cast<float2*>(outF + czB + ra*N_ + col) = make_float2(v0, v1);
                *reinterpret_cast<float2*>(outF + czB + rb*N_ + col) = make_float2(v2, v3);
            }
            if (outH) {
                *reinterpret_cast<uint32_t*>(outH + czB + ra*N_ + col) =
                    pack2(__float2half_rn(v0), __float2half_rn(v1));
                *reinterpret_cast<uint32_t*>(outH + czB + rb*N_ + col) =
                    pack2(__float2half_rn(v2), __float2half_rn(v3));
            }
        }
    }
}

// fp32 -> fp16 elementwise
__global__ void __launch_bounds__(256) conv_h(
    const float* __restrict__ in, __half* __restrict__ oh, int n4)
{
    int i = blockIdx.x * 256 + threadIdx.x;
    if (i >= n4) return;
    float4 v = reinterpret_cast<const float4*>(in)[i];
    reinterpret_cast<uint2*>(oh)[i] = make_uint2(
        pack2(__float2half_rn(v.x), __float2half_rn(v.y)),
        pack2(__float2half_rn(v.z), __float2half_rn(v.w)));
}

// transpose + fp16: in fp32 [R,C] -> out fp16 [C,R]
__global__ void tconv(
    const float* __restrict__ in,
    __half* __restrict__ oh,
    int R, int C)
{
    __shared__ float t[32][33];
    const int c0 = blockIdx.x * 32, r0 = blockIdx.y * 32;
#pragma unroll
    for (int dy = 0; dy < 32; dy += 8)
        t[threadIdx.y + dy][threadIdx.x] =
            in[(long long)(r0 + threadIdx.y + dy) * C + c0 + threadIdx.x];
    __syncthreads();
#pragma unroll
    for (int dy = 0; dy < 32; dy += 8) {
        float v = t[threadIdx.x][threadIdx.y + dy];
        long long o = (long long)(c0 + threadIdx.y + dy) * R + r0 + threadIdx.x;
        oh[o] = __float2half_rn(v);
    }
}

// fp16 transpose: in [R rows, ldIn] (C cols used) -> out [C, R]; batched z
__global__ void tconvh(
    const __half* __restrict__ in, long long ldIn, long long sIn,
    __half* __restrict__ oh, long long sOut,
    int R, int C)
{
    __shared__ __half t[32][34];
    const int c0 = blockIdx.x * 32, r0 = blockIdx.y * 32;
    in += blockIdx.z * sIn; oh += blockIdx.z * sOut;
#pragma unroll
    for (int dy = 0; dy < 32; dy += 8)
        t[threadIdx.y + dy][threadIdx.x] =
            in[(long long)(r0 + threadIdx.y + dy) * ldIn + c0 + threadIdx.x];
    __syncthreads();
#pragma unroll
    for (int dy = 0; dy < 32; dy += 8) {
        long long o = (long long)(c0 + threadIdx.y + dy) * R + r0 + threadIdx.x;
        oh[o] = t[threadIdx.x][threadIdx.y + dy];
    }
}

// concat 3 biases -> g_qkvb
__global__ void bias_cat(const float* __restrict__ qb, const float* __restrict__ kb,
                         const float* __restrict__ vb, float* __restrict__ o)
{
    int i = blockIdx.x * 256 + threadIdx.x;
    if (i < DMODEL)            o[i] = qb[i];
    else if (i < 2*DMODEL)     o[i] = kb[i - DMODEL];
    else if (i < 3*DMODEL)     o[i] = vb[i - 2*DMODEL];
}

// softmax over 4096 fp16 in place
__global__ void __launch_bounds__(256) softmax_k(__half* __restrict__ S)
{
    const long long row = blockIdx.x;
    __half* p = S + row * (long long)SEQ;
    const int tid = threadIdx.x, lane = tid & 31, warp = tid >> 5;
    __shared__ float red[8];

    float v[16];
    float mx = -1e30f;
#pragma unroll
    for (int i = 0; i < 16; i++) { v[i] = __half2float(p[i*256 + tid]); mx = fmaxf(mx, v[i]); }
#pragma unroll
    for (int o = 16; o > 0; o >>= 1) mx = fmaxf(mx, __shfl_xor_sync(0xffffffffu, mx, o));
    if (!lane) red[warp] = mx;
    __syncthreads();
    mx = red[0];
#pragma unroll
    for (int w = 1; w < 8; w++) mx = fmaxf(mx, red[w]);
    __syncthreads();
    float sm = 0.f;
#pragma unroll
    for (int i = 0; i < 16; i++) { v[i] = __expf(v[i] - mx); sm += v[i]; }
#pragma unroll
    for (int o = 16; o > 0; o >>= 1) sm += __shfl_xor_sync(0xffffffffu, sm, o);
    if (!lane) red[warp] = sm;
    __syncthreads();
    float inv = __frcp_rn(red[0]+red[1]+red[2]+red[3]+red[4]+red[5]+red[6]+red[7]);
#pragma unroll
    for (int i = 0; i < 16; i++)
        p[i*256 + tid] = __float2half_rn(v[i] * inv);
}

// out = LN(X+U); optionally fp16 too
template<bool HL>
__global__ void __launch_bounds__(128) add_ln_k(
    const float* __restrict__ X, const float* __restrict__ U,
    const float* __restrict__ g, const float* __restrict__ b,
    float* __restrict__ outF, __half* __restrict__ outH)
{
    const long long row = blockIdx.x;
    const int tid = threadIdx.x, lane = tid & 31, warp = tid >> 5;
    __shared__ float red[4];

    float4 xv = reinterpret_cast<const float4*>(X + row * DMODEL)[tid];
    float4 uv = reinterpret_cast<const float4*>(U + row * DMODEL)[tid];
    float4 s = make_float4(xv.x+uv.x, xv.y+uv.y, xv.z+uv.z, xv.w+uv.w);

    float pp = s.x + s.y + s.z + s.w;
#pragma unroll
    for (int o = 16; o > 0; o >>= 1) pp += __shfl_xor_sync(0xffffffffu, pp, o);
    if (!lane) red[warp] = pp;
    __syncthreads();
    float mu = (red[0]+red[1]+red[2]+red[3]) * (1.f/DMODEL);
    __syncthreads();
    float dx = s.x-mu, dy = s.y-mu, dz = s.z-mu, dw = s.w-mu;
    pp = dx*dx + dy*dy + dz*dz + dw*dw;
#pragma unroll
    for (int o = 16; o > 0; o >>= 1) pp += __shfl_xor_sync(0xffffffffu, pp, o);
    if (!lane) red[warp] = pp;
    __syncthreads();
    float inv = rsqrtf((red[0]+red[1]+red[2]+red[3]) * (1.f/DMODEL) + 1e-5f);

    float4 gv = reinterpret_cast<const float4*>(g)[tid];
    float4 bv = reinterpret_cast<const float4*>(b)[tid];
    float4 o4;
    o4.x = dx*inv*gv.x + bv.x;
    o4.y = dy*inv*gv.y + bv.y;
    o4.z = dz*inv*gv.z + bv.z;
    o4.w = dw*inv*gv.w + bv.w;
    reinterpret_cast<float4*>(outF + row * DMODEL)[tid] = o4;
    if (HL) {
        reinterpret_cast<uint2*>(outH + row * DMODEL)[tid] = make_uint2(
            pack2(__float2half_rn(o4.x), __float2half_rn(o4.y)),
            pack2(__float2half_rn(o4.z), __float2half_rn(o4.w)));
    }
}

// ---------------------------------------------------------------------------
extern "C" void kernel_launch(void* const* d_in, const int* in_sizes, int n_in,
                              void* d_out, int out_size)
{
    (void)in_sizes; (void)n_in; (void)out_size;
    const float* x     = (const float*)d_in[0];
    const float* Wq_w  = (const float*)d_in[1];
    const float* Wq_b  = (const float*)d_in[2];
    const float* Wk_w  = (const float*)d_in[3];
    const float* Wk_b  = (const float*)d_in[4];
    const float* Wv_w  = (const float*)d_in[5];
    const float* Wv_b  = (const float*)d_in[6];
    const float* Wu_w  = (const float*)d_in[7];
    const float* Wu_b  = (const float*)d_in[8];
    const float* ln1_g = (const float*)d_in[9];
    const float* ln1_b = (const float*)d_in[10];
    const float* ff1_w = (const float*)d_in[11];
    const float* ff1_b = (const float*)d_in[12];
    const float* ff2_w = (const float*)d_in[13];
    const float* ff2_b = (const float*)d_in[14];
    const float* ln2_g = (const float*)d_in[15];
    const float* ln2_b = (const float*)d_in[16];
    float* out = (float*)d_out;

#define SYM(T, n, s) T* n; { void* p_; cudaGetSymbolAddress(&p_, s); n = (T*)p_; }
    SYM(__half, s, g_s) SYM(float, u, g_u) SYM(float, h, g_h)
    SYM(__half, xh, g_xh)
    SYM(__half, qkv, g_qkv)
    SYM(__half, vth, g_vth)
    SYM(__half, ah, g_ah)
    SYM(__half, hh, g_hh)
    SYM(__half, fh, g_fh)
    SYM(__half, wqkv, g_wqkv)
    SYM(float,  qkvb, g_qkvb)
    SYM(__half, wuh, g_wuh)
    SYM(__half, f1h, g_f1h)
    SYM(__half, f2h, g_f2h)
#undef SYM

    const long long QS   = (long long)SEQ * DMODEL;          // 2M
    const long long SS   = (long long)SEQ * SEQ;             // 16.7M
    const long long QKVS = (long long)SEQ * NQKV;            // per-batch stride in qkv

    // 0: x -> fp16
    conv_h<<<(MTOT*DMODEL/4 + 255)/256, 256>>>(x, xh, MTOT*DMODEL/4);
    // 1-3: Wq|Wk|Wv transposed into combined [1536,512] fp16
    tconv<<<dim3(16,16,1), dim3(32,8)>>>(Wq_w, wqkv,                     DMODEL, DMODEL);
    tconv<<<dim3(16,16,1), dim3(32,8)>>>(Wk_w, wqkv + (size_t)DMODEL*DMODEL,   DMODEL, DMODEL);
    tconv<<<dim3(16,16,1), dim3(32,8)>>>(Wv_w, wqkv + (size_t)2*DMODEL*DMODEL, DMODEL, DMODEL);
    // 4: bias concat
    bias_cat<<<(NQKV + 255)/256, 256>>>(Wq_b, Wk_b, Wv_b, qkvb);

    // 5: fused QKV GEMM  [16384,1536] = xh @ wqkv^T + b   (ncu profile target)
    mma_gemm<false><<<dim3(NQKV/BNT, MTOT/BMT, 1), 256>>>(
        xh, DMODEL, 0, wqkv, DMODEL, 0, qkvb, 1.f, nullptr, qkv, NQKV, 0, DMODEL);

    // 6: scores = QK^T/8 -> fp16
    mma_gemm<false><<<dim3(SEQ/BNT, SEQ/BMT, BATCH), 256>>>(
        qkv, NQKV, QKVS, qkv + DMODEL, NQKV, QKVS,
        nullptr, 0.125f, nullptr, s, SEQ, SS, DMODEL);

    // 7: softmax fp16 in place
    softmax_k<<<MTOT, 256>>>(s);

    // 8: V^T per batch (fp16 in, V = qkv cols [1024,1536))
    tconvh<<<dim3(DMODEL/32, SEQ/32, BATCH), dim3(32,8)>>>(
        qkv + 2*DMODEL, NQKV, QKVS, vth, QS, SEQ, DMODEL);

    // 9: attn = P @ V
    mma_gemm<false><<<dim3(DMODEL/BNT, SEQ/BMT, BATCH), 256>>>(
        s, SEQ, SS, vth, SEQ, QS, nullptr, 1.f, nullptr, ah, DMODEL, QS, SEQ);

    // 10: Wu transpose
    tconv<<<dim3(16,16,1), dim3(32,8)>>>(Wu_w, wuh, DMODEL, DMODEL);
    // 11: unify
    mma_gemm<false><<<dim3(4,128,1), 256>>>(
        ah, DMODEL, 0, wuh, DMODEL, 0, Wu_b, 1.f, u, nullptr, DMODEL, 0, DMODEL);

    // 12: h = LN1(x+u)
    add_ln_k<true><<<MTOT, 128>>>(x, u, ln1_g, ln1_b, h, hh);

    // 13: ff1 weights; 14: ff1 (relu)
    tconv<<<dim3(FFDIM/32,16,1), dim3(32,8)>>>(ff1_w, f1h, DMODEL, FFDIM);
    mma_gemm<true><<<dim3(FFDIM/BNT,128,1), 256>>>(
        hh, DMODEL, 0, f1h, DMODEL, 0, ff1_b, 1.f, nullptr, fh, FFDIM, 0, DMODEL);

    // 15: ff2 weights; 16: ff2
    tconv<<<dim3(16,FFDIM/32,1), dim3(32,8)>>>(ff2_w, f2h, FFDIM, DMODEL);
    mma_gemm<false><<<dim3(4,128,1), 256>>>(
        fh, FFDIM, 0, f2h, FFDIM, 0, ff2_b, 1.f, u, nullptr, DMODEL, 0, FFDIM);

    // 17: out = LN2(h + ffwd)
    add_ln_k<false><<<MTOT, 128>>>(h, u, ln2_g, ln2_b, out, nullptr);
}